// round 1
// baseline (speedup 1.0000x reference)
#include <cuda_runtime.h>
#include <cuda_bf16.h>

// Problem constants
#define B_    2
#define SEQ   2048
#define DIM   2048
#define NH    16
#define HD    128
#define INNER 2048           // NH*HD
#define QK_SCALE 0.08838834764831845f   // 128^-0.5

// ---------------- scratch (device globals; no allocations allowed) ----------
__device__ float g_qproj[(size_t)B_ * SEQ * INNER];        //  33.5 MB
__device__ float g_kv  [(size_t)B_ * SEQ * 2 * INNER];     //  67.1 MB
__device__ float g_q   [(size_t)B_ * NH * SEQ * HD];       //  33.5 MB (b,h,n,d) rotated+scaled
__device__ float g_k   [(size_t)B_ * NH * SEQ * HD];       //  33.5 MB
__device__ float g_v   [(size_t)B_ * NH * SEQ * HD];       //  33.5 MB
__device__ float g_ao  [(size_t)B_ * SEQ * INNER];         //  33.5 MB attention out (b,n,h*d)

// ---------------------------------------------------------------------------
// Generic tiled SGEMM: C[M,N] = A[M,K] @ B[K,N] (+ bias[N]).  Row-major.
// BM=BN=64, BK=16, 256 threads, 4x4 micro-tile per thread.
// M % 64 == 0, N % 64 == 0, K % 16 == 0 (true for all our shapes).
// ---------------------------------------------------------------------------
__global__ __launch_bounds__(256) void sgemm64(
    const float* __restrict__ A, const float* __restrict__ Bm,
    float* __restrict__ C, int M, int N, int K,
    const float* __restrict__ bias)
{
    __shared__ float As[16][68];   // A^T tile, padded (68) to soften STS conflicts
    __shared__ float Bs[16][64];

    const int bn = blockIdx.x * 64;
    const int bm = blockIdx.y * 64;
    const int tid = threadIdx.x;
    const int tx = tid & 15;       // 0..15  -> N micro
    const int ty = tid >> 4;       // 0..15  -> M micro

    float acc[4][4] = {};

    for (int k0 = 0; k0 < K; k0 += 16) {
        // --- load A tile: 64 rows x 16 k, one float4 per thread along k
        {
            int m  = tid >> 2;          // 0..63
            int kq = tid & 3;           // 0..3  (float4 group)
            float4 a = *(const float4*)&A[(size_t)(bm + m) * K + k0 + kq * 4];
            As[kq * 4 + 0][m] = a.x;
            As[kq * 4 + 1][m] = a.y;
            As[kq * 4 + 2][m] = a.z;
            As[kq * 4 + 3][m] = a.w;
        }
        // --- load B tile: 16 k x 64 n, one float4 per thread along n
        {
            int k  = tid >> 4;          // 0..15
            int n4 = tid & 15;          // 0..15
            float4 b = *(const float4*)&Bm[(size_t)(k0 + k) * N + bn + n4 * 4];
            *(float4*)&Bs[k][n4 * 4] = b;
        }
        __syncthreads();

        #pragma unroll
        for (int k = 0; k < 16; k++) {
            float4 a4 = *(const float4*)&As[k][ty * 4];
            float4 b4 = *(const float4*)&Bs[k][tx * 4];
            acc[0][0] += a4.x * b4.x; acc[0][1] += a4.x * b4.y;
            acc[0][2] += a4.x * b4.z; acc[0][3] += a4.x * b4.w;
            acc[1][0] += a4.y * b4.x; acc[1][1] += a4.y * b4.y;
            acc[1][2] += a4.y * b4.z; acc[1][3] += a4.y * b4.w;
            acc[2][0] += a4.z * b4.x; acc[2][1] += a4.z * b4.y;
            acc[2][2] += a4.z * b4.z; acc[2][3] += a4.z * b4.w;
            acc[3][0] += a4.w * b4.x; acc[3][1] += a4.w * b4.y;
            acc[3][2] += a4.w * b4.z; acc[3][3] += a4.w * b4.w;
        }
        __syncthreads();
    }

    #pragma unroll
    for (int r = 0; r < 4; r++) {
        size_t row = (size_t)(bm + ty * 4 + r) * N;
        #pragma unroll
        for (int c = 0; c < 4; c++) {
            int col = bn + tx * 4 + c;
            float v = acc[r][c];
            if (bias) v += bias[col];
            C[row + col] = v;
        }
    }
}

// ---------------------------------------------------------------------------
// Rotary + layout transform: (b,n,h*d) -> (b,h,n,d); q scaled by QK_SCALE.
// rotate_half: out[2i] = t[2i]*cos - t[2i+1]*sin ; out[2i+1] = t[2i+1]*cos + t[2i]*sin
// ---------------------------------------------------------------------------
__global__ __launch_bounds__(256) void rotary_kernel(
    const float* __restrict__ qp, const float* __restrict__ kvp,
    const float* __restrict__ freqs)
{
    int i = blockIdx.x * blockDim.x + threadIdx.x;
    const int total = B_ * NH * SEQ * (HD / 2);
    if (i >= total) return;

    int p = i & (HD / 2 - 1);          // pair index 0..63
    int r = i >> 6;
    int n = r & (SEQ - 1); r >>= 11;
    int h = r & (NH - 1);
    int b = r >> 4;
    int d0 = 2 * p;

    float f0 = freqs[n * HD + d0];
    float f1 = freqs[n * HD + d0 + 1];
    float c0 = cosf(f0), s0 = sinf(f0);
    float c1 = cosf(f1), s1 = sinf(f1);

    size_t qsrc = ((size_t)b * SEQ + n) * INNER + h * HD + d0;
    size_t ksrc = ((size_t)b * SEQ + n) * (2 * INNER) + h * HD + d0;
    size_t dst  = (((size_t)b * NH + h) * SEQ + n) * HD + d0;

    float q0 = qp[qsrc], q1 = qp[qsrc + 1];
    g_q[dst]     = (q0 * c0 - q1 * s0) * QK_SCALE;
    g_q[dst + 1] = (q1 * c1 + q0 * s1) * QK_SCALE;

    float k0 = kvp[ksrc], k1 = kvp[ksrc + 1];
    g_k[dst]     = k0 * c0 - k1 * s0;
    g_k[dst + 1] = k1 * c1 + k0 * s1;

    g_v[dst]     = kvp[ksrc + INNER];
    g_v[dst + 1] = kvp[ksrc + INNER + 1];
}

// ---------------------------------------------------------------------------
// Flash attention (fp32, online softmax).
// grid = (SEQ/64, B_*NH), 256 threads.
// BM=64 query rows per CTA, BN=64 key tile, D=128.
// Thread (ty,tx) 16x16: S micro 4x4 (cols tx*4), O micro 4x8 (cols tx*8).
// ---------------------------------------------------------------------------
#define FBM 64
#define FBN 64
#define KVS (HD + 4)   // padded K/V row (132 floats)
#define SSW 68         // padded S row

__global__ __launch_bounds__(256) void flash_kernel()
{
    extern __shared__ float smem[];
    float* sQ  = smem;                          // FBM * HD          = 8192
    float* sKV = sQ + FBM * HD;                 // FBN * KVS         = 8448
    float* sS  = sKV + FBN * KVS;               // FBM * SSW         = 4352
    float* sM  = sS + FBM * SSW;                // 64
    float* sL  = sM + FBM;                      // 64
    float* sAl = sL + FBM;                      // 64

    const int qt = blockIdx.x;                  // query tile
    const int bh = blockIdx.y;                  // b*NH + h
    const int tid = threadIdx.x;
    const int tx = tid & 15;
    const int ty = tid >> 4;

    const float* Q  = g_q + ((size_t)bh * SEQ + qt * FBM) * HD;
    const float* Kp = g_k + (size_t)bh * SEQ * HD;
    const float* Vp = g_v + (size_t)bh * SEQ * HD;

    // load Q tile (contiguous)
    for (int i = tid; i < FBM * HD / 4; i += 256)
        ((float4*)sQ)[i] = ((const float4*)Q)[i];
    if (tid < FBM) { sM[tid] = -1e30f; sL[tid] = 0.f; }

    float acc[4][8] = {};
    __syncthreads();

    for (int j = 0; j < SEQ; j += FBN) {
        // ---- load K tile (row-padded)
        {
            const float4* src = (const float4*)(Kp + (size_t)j * HD);
            for (int i = tid; i < FBN * (HD / 4); i += 256) {
                int row = i >> 5, c4 = i & 31;
                *(float4*)&sKV[row * KVS + c4 * 4] = src[i];
            }
        }
        __syncthreads();

        // ---- S = Q K^T (4x4 micro)
        float s[4][4] = {};
        #pragma unroll 4
        for (int k = 0; k < HD; k += 4) {
            float4 a0 = *(const float4*)&sQ[(ty * 4 + 0) * HD + k];
            float4 a1 = *(const float4*)&sQ[(ty * 4 + 1) * HD + k];
            float4 a2 = *(const float4*)&sQ[(ty * 4 + 2) * HD + k];
            float4 a3 = *(const float4*)&sQ[(ty * 4 + 3) * HD + k];
            float4 b0 = *(const float4*)&sKV[(tx * 4 + 0) * KVS + k];
            float4 b1 = *(const float4*)&sKV[(tx * 4 + 1) * KVS + k];
            float4 b2 = *(const float4*)&sKV[(tx * 4 + 2) * KVS + k];
            float4 b3 = *(const float4*)&sKV[(tx * 4 + 3) * KVS + k];
            s[0][0] += a0.x*b0.x + a0.y*b0.y + a0.z*b0.z + a0.w*b0.w;
            s[0][1] += a0.x*b1.x + a0.y*b1.y + a0.z*b1.z + a0.w*b1.w;
            s[0][2] += a0.x*b2.x + a0.y*b2.y + a0.z*b2.z + a0.w*b2.w;
            s[0][3] += a0.x*b3.x + a0.y*b3.y + a0.z*b3.z + a0.w*b3.w;
            s[1][0] += a1.x*b0.x + a1.y*b0.y + a1.z*b0.z + a1.w*b0.w;
            s[1][1] += a1.x*b1.x + a1.y*b1.y + a1.z*b1.z + a1.w*b1.w;
            s[1][2] += a1.x*b2.x + a1.y*b2.y + a1.z*b2.z + a1.w*b2.w;
            s[1][3] += a1.x*b3.x + a1.y*b3.y + a1.z*b3.z + a1.w*b3.w;
            s[2][0] += a2.x*b0.x + a2.y*b0.y + a2.z*b0.z + a2.w*b0.w;
            s[2][1] += a2.x*b1.x + a2.y*b1.y + a2.z*b1.z + a2.w*b1.w;
            s[2][2] += a2.x*b2.x + a2.y*b2.y + a2.z*b2.z + a2.w*b2.w;
            s[2][3] += a2.x*b3.x + a2.y*b3.y + a2.z*b3.z + a2.w*b3.w;
            s[3][0] += a3.x*b0.x + a3.y*b0.y + a3.z*b0.z + a3.w*b0.w;
            s[3][1] += a3.x*b1.x + a3.y*b1.y + a3.z*b1.z + a3.w*b1.w;
            s[3][2] += a3.x*b2.x + a3.y*b2.y + a3.z*b2.z + a3.w*b2.w;
            s[3][3] += a3.x*b3.x + a3.y*b3.y + a3.z*b3.z + a3.w*b3.w;
        }
        #pragma unroll
        for (int r = 0; r < 4; r++)
            *(float4*)&sS[(ty * 4 + r) * SSW + tx * 4] =
                make_float4(s[r][0], s[r][1], s[r][2], s[r][3]);
        __syncthreads();

        // ---- online softmax: one thread per row (first 64 threads)
        if (tid < FBM) {
            float mold = sM[tid];
            float mrow = mold;
            #pragma unroll 8
            for (int c = 0; c < FBN; c++)
                mrow = fmaxf(mrow, sS[tid * SSW + c]);
            float alpha = __expf(mold - mrow);
            float lsum = 0.f;
            #pragma unroll 8
            for (int c = 0; c < FBN; c++) {
                float p = __expf(sS[tid * SSW + c] - mrow);
                sS[tid * SSW + c] = p;
                lsum += p;
            }
            sM[tid] = mrow;
            sL[tid] = sL[tid] * alpha + lsum;
            sAl[tid] = alpha;
        }
        __syncthreads();

        // ---- rescale accumulator
        #pragma unroll
        for (int r = 0; r < 4; r++) {
            float al = sAl[ty * 4 + r];
            #pragma unroll
            for (int c = 0; c < 8; c++) acc[r][c] *= al;
        }

        // ---- load V tile (overwrites K buffer; all K reads are done)
        {
            const float4* src = (const float4*)(Vp + (size_t)j * HD);
            for (int i = tid; i < FBN * (HD / 4); i += 256) {
                int row = i >> 5, c4 = i & 31;
                *(float4*)&sKV[row * KVS + c4 * 4] = src[i];
            }
        }
        __syncthreads();

        // ---- O += P @ V  (4 rows x 8 cols per thread)
        #pragma unroll 4
        for (int k = 0; k < FBN; k++) {
            float p0 = sS[(ty * 4 + 0) * SSW + k];
            float p1 = sS[(ty * 4 + 1) * SSW + k];
            float p2 = sS[(ty * 4 + 2) * SSW + k];
            float p3 = sS[(ty * 4 + 3) * SSW + k];
            float4 v0 = *(const float4*)&sKV[k * KVS + tx * 8];
            float4 v1 = *(const float4*)&sKV[k * KVS + tx * 8 + 4];
            acc[0][0] += p0*v0.x; acc[0][1] += p0*v0.y; acc[0][2] += p0*v0.z; acc[0][3] += p0*v0.w;
            acc[0][4] += p0*v1.x; acc[0][5] += p0*v1.y; acc[0][6] += p0*v1.z; acc[0][7] += p0*v1.w;
            acc[1][0] += p1*v0.x; acc[1][1] += p1*v0.y; acc[1][2] += p1*v0.z; acc[1][3] += p1*v0.w;
            acc[1][4] += p1*v1.x; acc[1][5] += p1*v1.y; acc[1][6] += p1*v1.z; acc[1][7] += p1*v1.w;
            acc[2][0] += p2*v0.x; acc[2][1] += p2*v0.y; acc[2][2] += p2*v0.z; acc[2][3] += p2*v0.w;
            acc[2][4] += p2*v1.x; acc[2][5] += p2*v1.y; acc[2][6] += p2*v1.z; acc[2][7] += p2*v1.w;
            acc[3][0] += p3*v0.x; acc[3][1] += p3*v0.y; acc[3][2] += p3*v0.z; acc[3][3] += p3*v0.w;
            acc[3][4] += p3*v1.x; acc[3][5] += p3*v1.y; acc[3][6] += p3*v1.z; acc[3][7] += p3*v1.w;
        }
        __syncthreads();   // before next iteration overwrites sKV with K
    }

    // ---- epilogue: normalize and write to (b,n,h*d)
    const int b = bh >> 4;
    const int h = bh & 15;
    #pragma unroll
    for (int r = 0; r < 4; r++) {
        float inv = 1.f / sL[ty * 4 + r];
        int n = qt * FBM + ty * 4 + r;
        size_t dst = ((size_t)b * SEQ + n) * INNER + h * HD + tx * 8;
        #pragma unroll
        for (int c = 0; c < 8; c++)
            g_ao[dst + c] = acc[r][c] * inv;
    }
}

// ---------------------------------------------------------------------------
extern "C" void kernel_launch(void* const* d_in, const int* in_sizes, int n_in,
                              void* d_out, int out_size)
{
    const float* x    = (const float*)d_in[0];
    const float* rot  = (const float*)d_in[1];
    const float* Wq   = (const float*)d_in[2];
    const float* Wkv  = (const float*)d_in[3];
    const float* Wo   = (const float*)d_in[4];
    const float* bo   = (const float*)d_in[5];
    float* out = (float*)d_out;

    float *qproj, *kv, *ao;
    cudaGetSymbolAddress((void**)&qproj, g_qproj);
    cudaGetSymbolAddress((void**)&kv,   g_kv);
    cudaGetSymbolAddress((void**)&ao,   g_ao);

    const int M = B_ * SEQ;   // 4096

    // 1) Q = x @ Wq
    sgemm64<<<dim3(INNER / 64, M / 64), 256>>>(x, Wq, qproj, M, INNER, DIM, nullptr);
    // 2) KV = x @ Wkv
    sgemm64<<<dim3(2 * INNER / 64, M / 64), 256>>>(x, Wkv, kv, M, 2 * INNER, DIM, nullptr);
    // 3) rotary + layout
    {
        int total = B_ * NH * SEQ * (HD / 2);
        rotary_kernel<<<total / 256, 256>>>(qproj, kv, rot);
    }
    // 4) flash attention
    {
        size_t smem = (size_t)(FBM * HD + FBN * KVS + FBM * SSW + 3 * FBM) * sizeof(float);
        cudaFuncSetAttribute(flash_kernel, cudaFuncAttributeMaxDynamicSharedMemorySize, (int)smem);
        flash_kernel<<<dim3(SEQ / FBM, B_ * NH), 256, smem>>>();
    }
    // 5) out = ao @ Wo + bo
    sgemm64<<<dim3(DIM / 64, M / 64), 256>>>(ao, Wo, out, M, DIM, INNER, bo);
}

// round 4
// speedup vs baseline: 1.6398x; 1.6398x over previous
#include <cuda_runtime.h>
#include <cuda_bf16.h>
#include <cstdint>

// Problem constants
#define B_    2
#define SEQ   2048
#define DIM   2048
#define NH    16
#define HD    128
#define INNER 2048           // NH*HD
#define QK_SCALE 0.08838834764831845f   // 128^-0.5

// ---------------- scratch (device globals; no allocations allowed) ----------
__device__ float g_qproj[(size_t)B_ * SEQ * INNER];
__device__ float g_kv  [(size_t)B_ * SEQ * 2 * INNER];
__device__ float g_q   [(size_t)B_ * NH * SEQ * HD];   // (b,h,n,d) rotated+scaled
__device__ float g_k   [(size_t)B_ * NH * SEQ * HD];
__device__ float g_v   [(size_t)B_ * NH * SEQ * HD];
__device__ float g_ao  [(size_t)B_ * SEQ * INNER];     // attention out (b,n,h*d)

// ---------------------------------------------------------------------------
// tf32 helpers
// ---------------------------------------------------------------------------
__device__ __forceinline__ uint32_t f2tf32(float f) {
    uint32_t u;
    asm("cvt.rna.tf32.f32 %0, %1;" : "=r"(u) : "f"(f));
    return u;
}
__device__ __forceinline__ float tf32_round(float f) {
    return __uint_as_float(f2tf32(f));
}
__device__ __forceinline__ void mma_tf32(float* d, const uint32_t* a,
                                         uint32_t b0, uint32_t b1) {
    asm volatile(
        "mma.sync.aligned.m16n8k8.row.col.f32.tf32.tf32.f32 "
        "{%0,%1,%2,%3}, {%4,%5,%6,%7}, {%8,%9}, {%0,%1,%2,%3};"
        : "+f"(d[0]), "+f"(d[1]), "+f"(d[2]), "+f"(d[3])
        : "r"(a[0]), "r"(a[1]), "r"(a[2]), "r"(a[3]), "r"(b0), "r"(b1));
}

// ---------------------------------------------------------------------------
// 3xTF32 GEMM: C[M,N] = A[M,K] @ B[K,N] (+bias). BM=BN=128, BK=16, 256 thr.
// 8 warps: warp tile 64(m) x 32(n). fp32-grade accuracy via hi/lo split.
// ---------------------------------------------------------------------------
#define ASTR 20
#define BSTR 136

__global__ __launch_bounds__(256, 1) void mma_gemm(
    const float* __restrict__ A, const float* __restrict__ Bm,
    float* __restrict__ C, int M, int N, int K,
    const float* __restrict__ bias)
{
    __shared__ float sAh[128][ASTR], sAl[128][ASTR];
    __shared__ float sBh[16][BSTR],  sBl[16][BSTR];

    const int bm = blockIdx.y * 128;
    const int bn = blockIdx.x * 128;
    const int tid = threadIdx.x;
    const int wid = tid >> 5, lane = tid & 31;
    const int wm = (wid & 1) * 64;      // warp m offset
    const int wn = (wid >> 1) * 32;     // warp n offset
    const int gq = lane >> 2;           // groupID
    const int tg = lane & 3;            // thread-in-group

    float acc[4][4][4] = {};            // [m-atom][n-atom][reg]

    for (int k0 = 0; k0 < K; k0 += 16) {
        // stage A tile 128x16, split hi/lo
        #pragma unroll
        for (int i = tid; i < 512; i += 256) {
            int r = i >> 2, q = i & 3;
            float4 a = *(const float4*)&A[(size_t)(bm + r) * K + k0 + q * 4];
            float v[4] = {a.x, a.y, a.z, a.w};
            #pragma unroll
            for (int j = 0; j < 4; j++) {
                float hi = tf32_round(v[j]);
                sAh[r][q * 4 + j] = hi;
                sAl[r][q * 4 + j] = tf32_round(v[j] - hi);
            }
        }
        // stage B tile 16x128, split hi/lo
        #pragma unroll
        for (int i = tid; i < 512; i += 256) {
            int r = i >> 5, q = i & 31;
            float4 b = *(const float4*)&Bm[(size_t)(k0 + r) * N + bn + q * 4];
            float v[4] = {b.x, b.y, b.z, b.w};
            #pragma unroll
            for (int j = 0; j < 4; j++) {
                float hi = tf32_round(v[j]);
                sBh[r][q * 4 + j] = hi;
                sBl[r][q * 4 + j] = tf32_round(v[j] - hi);
            }
        }
        __syncthreads();

        #pragma unroll
        for (int kk = 0; kk < 2; kk++) {
            const int kb = kk * 8;
            uint32_t ah[4][4], al[4][4];
            #pragma unroll
            for (int ma = 0; ma < 4; ma++) {
                int r0 = wm + ma * 16 + gq;
                ah[ma][0] = __float_as_uint(sAh[r0    ][kb + tg    ]);
                ah[ma][1] = __float_as_uint(sAh[r0 + 8][kb + tg    ]);
                ah[ma][2] = __float_as_uint(sAh[r0    ][kb + tg + 4]);
                ah[ma][3] = __float_as_uint(sAh[r0 + 8][kb + tg + 4]);
                al[ma][0] = __float_as_uint(sAl[r0    ][kb + tg    ]);
                al[ma][1] = __float_as_uint(sAl[r0 + 8][kb + tg    ]);
                al[ma][2] = __float_as_uint(sAl[r0    ][kb + tg + 4]);
                al[ma][3] = __float_as_uint(sAl[r0 + 8][kb + tg + 4]);
            }
            #pragma unroll
            for (int na = 0; na < 4; na++) {
                int c0 = wn + na * 8 + gq;
                uint32_t bh0 = __float_as_uint(sBh[kb + tg    ][c0]);
                uint32_t bh1 = __float_as_uint(sBh[kb + tg + 4][c0]);
                uint32_t bl0 = __float_as_uint(sBl[kb + tg    ][c0]);
                uint32_t bl1 = __float_as_uint(sBl[kb + tg + 4][c0]);
                #pragma unroll
                for (int ma = 0; ma < 4; ma++) {
                    mma_tf32(acc[ma][na], ah[ma], bh0, bh1);
                    mma_tf32(acc[ma][na], ah[ma], bl0, bl1);
                    mma_tf32(acc[ma][na], al[ma], bh0, bh1);
                }
            }
        }
        __syncthreads();
    }

    // epilogue
    #pragma unroll
    for (int ma = 0; ma < 4; ma++) {
        int r0 = bm + wm + ma * 16 + gq;
        #pragma unroll
        for (int na = 0; na < 4; na++) {
            int c = bn + wn + na * 8 + 2 * tg;
            float b0 = bias ? bias[c] : 0.f;
            float b1 = bias ? bias[c + 1] : 0.f;
            C[(size_t)r0 * N + c]           = acc[ma][na][0] + b0;
            C[(size_t)r0 * N + c + 1]       = acc[ma][na][1] + b1;
            C[(size_t)(r0 + 8) * N + c]     = acc[ma][na][2] + b0;
            C[(size_t)(r0 + 8) * N + c + 1] = acc[ma][na][3] + b1;
        }
    }
}

// ---------------------------------------------------------------------------
// Rotary + layout transform: (b,n,h*d) -> (b,h,n,d); q scaled by QK_SCALE.
// ---------------------------------------------------------------------------
__global__ __launch_bounds__(256) void rotary_kernel(
    const float* __restrict__ qp, const float* __restrict__ kvp,
    const float* __restrict__ freqs)
{
    int i = blockIdx.x * blockDim.x + threadIdx.x;
    const int total = B_ * NH * SEQ * (HD / 2);
    if (i >= total) return;

    int p = i & (HD / 2 - 1);
    int r = i >> 6;
    int n = r & (SEQ - 1); r >>= 11;
    int h = r & (NH - 1);
    int b = r >> 4;
    int d0 = 2 * p;

    float f0 = freqs[n * HD + d0];
    float f1 = freqs[n * HD + d0 + 1];
    float c0 = cosf(f0), s0 = sinf(f0);
    float c1 = cosf(f1), s1 = sinf(f1);

    size_t qsrc = ((size_t)b * SEQ + n) * INNER + h * HD + d0;
    size_t ksrc = ((size_t)b * SEQ + n) * (2 * INNER) + h * HD + d0;
    size_t dst  = (((size_t)b * NH + h) * SEQ + n) * HD + d0;

    float q0 = qp[qsrc], q1 = qp[qsrc + 1];
    g_q[dst]     = (q0 * c0 - q1 * s0) * QK_SCALE;
    g_q[dst + 1] = (q1 * c1 + q0 * s1) * QK_SCALE;

    float k0 = kvp[ksrc], k1 = kvp[ksrc + 1];
    g_k[dst]     = k0 * c0 - k1 * s0;
    g_k[dst + 1] = k1 * c1 + k0 * s1;

    g_v[dst]     = kvp[ksrc + INNER];
    g_v[dst + 1] = kvp[ksrc + INNER + 1];
}

// ---------------------------------------------------------------------------
// Flash attention with tf32 mma. BM=64 (4 warps x 16 rows), BN=64, D=128.
// Q/K/V/P pre-rounded to tf32 at smem stage (single-pass tf32).
// ---------------------------------------------------------------------------
#define QSTR 132
#define KSTR 132
#define VSTR 136
#define PSTR 68

__global__ __launch_bounds__(128, 1) void flash_mma()
{
    extern __shared__ float smem[];
    float* sQ  = smem;                    // 64*QSTR
    float* sKV = sQ + 64 * QSTR;          // 64*VSTR (K: stride 132, V: stride 136)
    float* sP  = sKV + 64 * VSTR;         // 64*PSTR

    const int qt  = blockIdx.x;           // query tile
    const int bh  = blockIdx.y;           // b*NH + h
    const int tid = threadIdx.x;
    const int wid = tid >> 5, lane = tid & 31;
    const int gq = lane >> 2, tg = lane & 3;
    const int wrow = wid * 16;            // warp's query-row base in tile

    const float* Q  = g_q + ((size_t)bh * SEQ + (size_t)qt * 64) * HD;
    const float* Kp = g_k + (size_t)bh * SEQ * HD;
    const float* Vp = g_v + (size_t)bh * SEQ * HD;

    // load + round Q tile (64 x 128)
    for (int i = tid; i < 64 * 32; i += 128) {
        int r = i >> 5, q = i & 31;
        float4 v = *(const float4*)&Q[(size_t)r * HD + q * 4];
        sQ[r * QSTR + q * 4 + 0] = tf32_round(v.x);
        sQ[r * QSTR + q * 4 + 1] = tf32_round(v.y);
        sQ[r * QSTR + q * 4 + 2] = tf32_round(v.z);
        sQ[r * QSTR + q * 4 + 3] = tf32_round(v.w);
    }

    float oacc[16][4] = {};               // O: 16 rows x 128 cols per warp
    float m0 = -1e30f, m1 = -1e30f, l0 = 0.f, l1 = 0.f;
    __syncthreads();

    for (int j = 0; j < SEQ; j += 64) {
        // ---- K tile
        for (int i = tid; i < 64 * 32; i += 128) {
            int r = i >> 5, q = i & 31;
            float4 v = *(const float4*)&Kp[(size_t)(j + r) * HD + q * 4];
            sKV[r * KSTR + q * 4 + 0] = tf32_round(v.x);
            sKV[r * KSTR + q * 4 + 1] = tf32_round(v.y);
            sKV[r * KSTR + q * 4 + 2] = tf32_round(v.z);
            sKV[r * KSTR + q * 4 + 3] = tf32_round(v.w);
        }
        __syncthreads();

        // ---- S = Q K^T : 8 n-atoms x 16 k-atoms
        float sacc[8][4] = {};
        #pragma unroll
        for (int ka = 0; ka < 16; ka++) {
            const int kb = ka * 8;
            uint32_t a[4];
            a[0] = __float_as_uint(sQ[(wrow + gq    ) * QSTR + kb + tg    ]);
            a[1] = __float_as_uint(sQ[(wrow + gq + 8) * QSTR + kb + tg    ]);
            a[2] = __float_as_uint(sQ[(wrow + gq    ) * QSTR + kb + tg + 4]);
            a[3] = __float_as_uint(sQ[(wrow + gq + 8) * QSTR + kb + tg + 4]);
            #pragma unroll
            for (int na = 0; na < 8; na++) {
                uint32_t b0 = __float_as_uint(sKV[(na * 8 + gq) * KSTR + kb + tg    ]);
                uint32_t b1 = __float_as_uint(sKV[(na * 8 + gq) * KSTR + kb + tg + 4]);
                mma_tf32(sacc[na], a, b0, b1);
            }
        }

        // ---- online softmax (rows: r0 = wrow+gq, r1 = wrow+gq+8)
        float rmax0 = -1e30f, rmax1 = -1e30f;
        #pragma unroll
        for (int na = 0; na < 8; na++) {
            rmax0 = fmaxf(rmax0, fmaxf(sacc[na][0], sacc[na][1]));
            rmax1 = fmaxf(rmax1, fmaxf(sacc[na][2], sacc[na][3]));
        }
        rmax0 = fmaxf(rmax0, __shfl_xor_sync(0xffffffffu, rmax0, 1));
        rmax0 = fmaxf(rmax0, __shfl_xor_sync(0xffffffffu, rmax0, 2));
        rmax1 = fmaxf(rmax1, __shfl_xor_sync(0xffffffffu, rmax1, 1));
        rmax1 = fmaxf(rmax1, __shfl_xor_sync(0xffffffffu, rmax1, 2));

        float nm0 = fmaxf(m0, rmax0), nm1 = fmaxf(m1, rmax1);
        float al0 = __expf(m0 - nm0), al1 = __expf(m1 - nm1);
        float ls0 = 0.f, ls1 = 0.f;
        #pragma unroll
        for (int na = 0; na < 8; na++) {
            float p0 = __expf(sacc[na][0] - nm0);
            float p1 = __expf(sacc[na][1] - nm0);
            float p2 = __expf(sacc[na][2] - nm1);
            float p3 = __expf(sacc[na][3] - nm1);
            ls0 += p0 + p1; ls1 += p2 + p3;
            int c = na * 8 + 2 * tg;
            sP[(wrow + gq    ) * PSTR + c    ] = tf32_round(p0);
            sP[(wrow + gq    ) * PSTR + c + 1] = tf32_round(p1);
            sP[(wrow + gq + 8) * PSTR + c    ] = tf32_round(p2);
            sP[(wrow + gq + 8) * PSTR + c + 1] = tf32_round(p3);
        }
        ls0 += __shfl_xor_sync(0xffffffffu, ls0, 1);
        ls0 += __shfl_xor_sync(0xffffffffu, ls0, 2);
        ls1 += __shfl_xor_sync(0xffffffffu, ls1, 1);
        ls1 += __shfl_xor_sync(0xffffffffu, ls1, 2);
        l0 = l0 * al0 + ls0;
        l1 = l1 * al1 + ls1;
        m0 = nm0; m1 = nm1;

        #pragma unroll
        for (int na = 0; na < 16; na++) {
            oacc[na][0] *= al0; oacc[na][1] *= al0;
            oacc[na][2] *= al1; oacc[na][3] *= al1;
        }
        __syncthreads();   // P written; all K-reads done

        // ---- V tile (overwrites K buffer, stride VSTR)
        for (int i = tid; i < 64 * 32; i += 128) {
            int r = i >> 5, q = i & 31;
            float4 v = *(const float4*)&Vp[(size_t)(j + r) * HD + q * 4];
            sKV[r * VSTR + q * 4 + 0] = tf32_round(v.x);
            sKV[r * VSTR + q * 4 + 1] = tf32_round(v.y);
            sKV[r * VSTR + q * 4 + 2] = tf32_round(v.z);
            sKV[r * VSTR + q * 4 + 3] = tf32_round(v.w);
        }
        __syncthreads();

        // ---- O += P @ V : 8 k-atoms x 16 n-atoms
        #pragma unroll
        for (int ka = 0; ka < 8; ka++) {
            const int kb = ka * 8;
            uint32_t a[4];
            a[0] = __float_as_uint(sP[(wrow + gq    ) * PSTR + kb + tg    ]);
            a[1] = __float_as_uint(sP[(wrow + gq + 8) * PSTR + kb + tg    ]);
            a[2] = __float_as_uint(sP[(wrow + gq    ) * PSTR + kb + tg + 4]);
            a[3] = __float_as_uint(sP[(wrow + gq + 8) * PSTR + kb + tg + 4]);
            #pragma unroll
            for (int na = 0; na < 16; na++) {
                uint32_t b0 = __float_as_uint(sKV[(kb + tg    ) * VSTR + na * 8 + gq]);
                uint32_t b1 = __float_as_uint(sKV[(kb + tg + 4) * VSTR + na * 8 + gq]);
                mma_tf32(oacc[na], a, b0, b1);
            }
        }
        __syncthreads();   // before next K tile overwrites sKV
    }

    // ---- epilogue: normalize, write to (b,n,h*d)
    const int b = bh >> 4, h = bh & 15;
    const float inv0 = 1.f / l0, inv1 = 1.f / l1;
    const int r0 = qt * 64 + wrow + gq;
    #pragma unroll
    for (int na = 0; na < 16; na++) {
        int c = h * HD + na * 8 + 2 * tg;
        size_t base0 = ((size_t)b * SEQ + r0) * INNER + c;
        size_t base1 = ((size_t)b * SEQ + r0 + 8) * INNER + c;
        g_ao[base0]     = oacc[na][0] * inv0;
        g_ao[base0 + 1] = oacc[na][1] * inv0;
        g_ao[base1]     = oacc[na][2] * inv1;
        g_ao[base1 + 1] = oacc[na][3] * inv1;
    }
}

// ---------------------------------------------------------------------------
extern "C" void kernel_launch(void* const* d_in, const int* in_sizes, int n_in,
                              void* d_out, int out_size)
{
    const float* x   = (const float*)d_in[0];
    const float* rot = (const float*)d_in[1];
    const float* Wq  = (const float*)d_in[2];
    const float* Wkv = (const float*)d_in[3];
    const float* Wo  = (const float*)d_in[4];
    const float* bo  = (const float*)d_in[5];
    float* out = (float*)d_out;

    float *qproj, *kv, *ao;
    cudaGetSymbolAddress((void**)&qproj, g_qproj);
    cudaGetSymbolAddress((void**)&kv,   g_kv);
    cudaGetSymbolAddress((void**)&ao,   g_ao);

    const int M = B_ * SEQ;   // 4096

    // 1) Q = x @ Wq
    mma_gemm<<<dim3(INNER / 128, M / 128), 256>>>(x, Wq, qproj, M, INNER, DIM, nullptr);
    // 2) KV = x @ Wkv
    mma_gemm<<<dim3(2 * INNER / 128, M / 128), 256>>>(x, Wkv, kv, M, 2 * INNER, DIM, nullptr);
    // 3) rotary + layout
    {
        int total = B_ * NH * SEQ * (HD / 2);
        rotary_kernel<<<total / 256, 256>>>(qproj, kv, rot);
    }
    // 4) flash attention (tf32 mma)
    {
        size_t smemb = (size_t)(64 * QSTR + 64 * VSTR + 64 * PSTR) * sizeof(float);
        cudaFuncSetAttribute(flash_mma, cudaFuncAttributeMaxDynamicSharedMemorySize, (int)smemb);
        flash_mma<<<dim3(SEQ / 64, B_ * NH), 128, smemb>>>();
    }
    // 5) out = ao @ Wo + bo
    mma_gemm<<<dim3(DIM / 128, M / 128), 256>>>(ao, Wo, out, M, DIM, INNER, bo);
}

// round 6
// speedup vs baseline: 2.5164x; 1.5345x over previous
#include <cuda_runtime.h>
#include <cuda_bf16.h>
#include <cstdint>

// Problem constants
#define B_    2
#define SEQ   2048
#define DIM   2048
#define NH    16
#define HD    128
#define INNER 2048           // NH*HD
#define QK_SCALE 0.08838834764831845f   // 128^-0.5

// ---------------- scratch (device globals; no allocations allowed) ----------
__device__ float g_qproj[(size_t)B_ * SEQ * INNER];
__device__ float g_kv  [(size_t)B_ * SEQ * 2 * INNER];
__device__ float g_q   [(size_t)B_ * NH * SEQ * HD];   // (b,h,n,d) rotated+scaled
__device__ float g_k   [(size_t)B_ * NH * SEQ * HD];
__device__ float g_v   [(size_t)B_ * NH * SEQ * HD];
__device__ float g_ao  [(size_t)B_ * SEQ * INNER];     // attention out (b,n,h*d)

// ---------------------------------------------------------------------------
// tf32 helpers (flash kernel)
// ---------------------------------------------------------------------------
__device__ __forceinline__ uint32_t f2tf32(float f) {
    uint32_t u;
    asm("cvt.rna.tf32.f32 %0, %1;" : "=r"(u) : "f"(f));
    return u;
}
__device__ __forceinline__ float tf32_round(float f) {
    return __uint_as_float(f2tf32(f));
}
__device__ __forceinline__ void mma_tf32(float* d, const uint32_t* a,
                                         uint32_t b0, uint32_t b1) {
    asm volatile(
        "mma.sync.aligned.m16n8k8.row.col.f32.tf32.tf32.f32 "
        "{%0,%1,%2,%3}, {%4,%5,%6,%7}, {%8,%9}, {%0,%1,%2,%3};"
        : "+f"(d[0]), "+f"(d[1]), "+f"(d[2]), "+f"(d[3])
        : "r"(a[0]), "r"(a[1]), "r"(a[2]), "r"(a[3]), "r"(b0), "r"(b1));
}

// ---------------------------------------------------------------------------
// bf16 helpers (GEMM)
// ---------------------------------------------------------------------------
__device__ __forceinline__ void mma_bf16(float* d, const uint32_t* a,
                                         uint32_t b0, uint32_t b1) {
    asm volatile(
        "mma.sync.aligned.m16n8k16.row.col.f32.bf16.bf16.f32 "
        "{%0,%1,%2,%3}, {%4,%5,%6,%7}, {%8,%9}, {%0,%1,%2,%3};"
        : "+f"(d[0]), "+f"(d[1]), "+f"(d[2]), "+f"(d[3])
        : "r"(a[0]), "r"(a[1]), "r"(a[2]), "r"(a[3]), "r"(b0), "r"(b1));
}

// ---------------------------------------------------------------------------
// 3xBF16 GEMM: C[M,N] = A[M,K] @ B[K,N] (+bias). BM=BN=128, BK=16, 256 thr.
// 8 warps: warp tile 64(m) x 32(n). Near-fp32 accuracy via bf16 hi/lo split
// (ah*bh + ah*bl + al*bh; dropped al*bl ~2^-18 rel).
// Double-buffered smem, register staging, ONE __syncthreads per k-tile.
// Smem holds packed bf16x2 k-pairs: A m-major, B transposed to n-major,
// so every mma fragment load is a single 32-bit LDS.
// ---------------------------------------------------------------------------
#define PADW 9   // 8 k-pair words + 1 pad

__global__ __launch_bounds__(256, 1) void gemm_bf16(
    const float* __restrict__ A, const float* __restrict__ Bm,
    float* __restrict__ C, int M, int N, int K,
    const float* __restrict__ bias)
{
    __shared__ uint32_t sAh[2][128][PADW], sAl[2][128][PADW];
    __shared__ uint32_t sBh[2][128][PADW], sBl[2][128][PADW];

    const int bm = blockIdx.y * 128;
    const int bn = blockIdx.x * 128;
    const int tid = threadIdx.x;
    const int wid = tid >> 5, lane = tid & 31;
    const int wm = (wid & 1) * 64;      // warp m offset
    const int wn = (wid >> 1) * 32;     // warp n offset
    const int gq = lane >> 2;           // groupID
    const int tg = lane & 3;            // thread-in-group

    // staging thread mapping
    const int r_a = tid >> 2, q_a = tid & 3;   // A: rows r_a, r_a+64; k-quad q_a
    const int k_b = tid >> 5, n4 = tid & 31;   // B: k rows k_b, k_b+8; n-quad n4

    float acc[4][4][4] = {};            // [m-atom][n-atom][reg]
    float4 ra0, ra1, rb0, rb1;

    // ---- prologue: load tile 0
    {
        ra0 = *(const float4*)&A[(size_t)(bm + r_a) * K + q_a * 4];
        ra1 = *(const float4*)&A[(size_t)(bm + r_a + 64) * K + q_a * 4];
        rb0 = *(const float4*)&Bm[(size_t)k_b * N + bn + n4 * 4];
        rb1 = *(const float4*)&Bm[(size_t)(k_b + 8) * N + bn + n4 * 4];
    }

    int buf = 0;
    // store tile 0 into buf 0
    {
        __nv_bfloat16* pAh0 = (__nv_bfloat16*)sAh[0][r_a];
        __nv_bfloat16* pAl0 = (__nv_bfloat16*)sAl[0][r_a];
        __nv_bfloat16* pAh1 = (__nv_bfloat16*)sAh[0][r_a + 64];
        __nv_bfloat16* pAl1 = (__nv_bfloat16*)sAl[0][r_a + 64];
        float v0[4] = {ra0.x, ra0.y, ra0.z, ra0.w};
        float v1[4] = {ra1.x, ra1.y, ra1.z, ra1.w};
        float w0[4] = {rb0.x, rb0.y, rb0.z, rb0.w};
        float w1[4] = {rb1.x, rb1.y, rb1.z, rb1.w};
        #pragma unroll
        for (int j = 0; j < 4; j++) {
            __nv_bfloat16 h = __float2bfloat16(v0[j]);
            pAh0[q_a * 4 + j] = h;
            pAl0[q_a * 4 + j] = __float2bfloat16(v0[j] - __bfloat162float(h));
            h = __float2bfloat16(v1[j]);
            pAh1[q_a * 4 + j] = h;
            pAl1[q_a * 4 + j] = __float2bfloat16(v1[j] - __bfloat162float(h));
            h = __float2bfloat16(w0[j]);
            ((__nv_bfloat16*)sBh[0][n4 * 4 + j])[k_b] = h;
            ((__nv_bfloat16*)sBl[0][n4 * 4 + j])[k_b] = __float2bfloat16(w0[j] - __bfloat162float(h));
            h = __float2bfloat16(w1[j]);
            ((__nv_bfloat16*)sBh[0][n4 * 4 + j])[k_b + 8] = h;
            ((__nv_bfloat16*)sBl[0][n4 * 4 + j])[k_b + 8] = __float2bfloat16(w1[j] - __bfloat162float(h));
        }
    }
    __syncthreads();

    for (int k0 = 0; k0 < K; k0 += 16) {
        const bool has_next = (k0 + 16) < K;
        // ---- prefetch next tile into registers (latency hidden under MMAs)
        if (has_next) {
            int kn = k0 + 16;
            ra0 = *(const float4*)&A[(size_t)(bm + r_a) * K + kn + q_a * 4];
            ra1 = *(const float4*)&A[(size_t)(bm + r_a + 64) * K + kn + q_a * 4];
            rb0 = *(const float4*)&Bm[(size_t)(kn + k_b) * N + bn + n4 * 4];
            rb1 = *(const float4*)&Bm[(size_t)(kn + k_b + 8) * N + bn + n4 * 4];
        }

        // ---- compute from current buffer
        {
            const uint32_t (*Ah)[PADW] = sAh[buf];
            const uint32_t (*Al)[PADW] = sAl[buf];
            const uint32_t (*Bh)[PADW] = sBh[buf];
            const uint32_t (*Bl)[PADW] = sBl[buf];

            uint32_t ah[4][4], al[4][4];
            #pragma unroll
            for (int ma = 0; ma < 4; ma++) {
                int r0 = wm + ma * 16 + gq;
                ah[ma][0] = Ah[r0    ][tg];     al[ma][0] = Al[r0    ][tg];
                ah[ma][1] = Ah[r0 + 8][tg];     al[ma][1] = Al[r0 + 8][tg];
                ah[ma][2] = Ah[r0    ][tg + 4]; al[ma][2] = Al[r0    ][tg + 4];
                ah[ma][3] = Ah[r0 + 8][tg + 4]; al[ma][3] = Al[r0 + 8][tg + 4];
            }
            #pragma unroll
            for (int na = 0; na < 4; na++) {
                int c0 = wn + na * 8 + gq;
                uint32_t bh0 = Bh[c0][tg], bh1 = Bh[c0][tg + 4];
                uint32_t bl0 = Bl[c0][tg], bl1 = Bl[c0][tg + 4];
                #pragma unroll
                for (int ma = 0; ma < 4; ma++) {
                    mma_bf16(acc[ma][na], ah[ma], bh0, bh1);
                    mma_bf16(acc[ma][na], ah[ma], bl0, bl1);
                    mma_bf16(acc[ma][na], al[ma], bh0, bh1);
                }
            }
        }

        // ---- write prefetched tile to other buffer; single sync
        if (has_next) {
            int nb = buf ^ 1;
            __nv_bfloat16* pAh0 = (__nv_bfloat16*)sAh[nb][r_a];
            __nv_bfloat16* pAl0 = (__nv_bfloat16*)sAl[nb][r_a];
            __nv_bfloat16* pAh1 = (__nv_bfloat16*)sAh[nb][r_a + 64];
            __nv_bfloat16* pAl1 = (__nv_bfloat16*)sAl[nb][r_a + 64];
            float v0[4] = {ra0.x, ra0.y, ra0.z, ra0.w};
            float v1[4] = {ra1.x, ra1.y, ra1.z, ra1.w};
            float w0[4] = {rb0.x, rb0.y, rb0.z, rb0.w};
            float w1[4] = {rb1.x, rb1.y, rb1.z, rb1.w};
            #pragma unroll
            for (int j = 0; j < 4; j++) {
                __nv_bfloat16 h = __float2bfloat16(v0[j]);
                pAh0[q_a * 4 + j] = h;
                pAl0[q_a * 4 + j] = __float2bfloat16(v0[j] - __bfloat162float(h));
                h = __float2bfloat16(v1[j]);
                pAh1[q_a * 4 + j] = h;
                pAl1[q_a * 4 + j] = __float2bfloat16(v1[j] - __bfloat162float(h));
                h = __float2bfloat16(w0[j]);
                ((__nv_bfloat16*)sBh[nb][n4 * 4 + j])[k_b] = h;
                ((__nv_bfloat16*)sBl[nb][n4 * 4 + j])[k_b] = __float2bfloat16(w0[j] - __bfloat162float(h));
                h = __float2bfloat16(w1[j]);
                ((__nv_bfloat16*)sBh[nb][n4 * 4 + j])[k_b + 8] = h;
                ((__nv_bfloat16*)sBl[nb][n4 * 4 + j])[k_b + 8] = __float2bfloat16(w1[j] - __bfloat162float(h));
            }
            __syncthreads();
            buf = nb;
        }
    }

    // ---- epilogue
    #pragma unroll
    for (int ma = 0; ma < 4; ma++) {
        int r0 = bm + wm + ma * 16 + gq;
        #pragma unroll
        for (int na = 0; na < 4; na++) {
            int c = bn + wn + na * 8 + 2 * tg;
            float b0 = bias ? bias[c] : 0.f;
            float b1 = bias ? bias[c + 1] : 0.f;
            C[(size_t)r0 * N + c]           = acc[ma][na][0] + b0;
            C[(size_t)r0 * N + c + 1]       = acc[ma][na][1] + b1;
            C[(size_t)(r0 + 8) * N + c]     = acc[ma][na][2] + b0;
            C[(size_t)(r0 + 8) * N + c + 1] = acc[ma][na][3] + b1;
        }
    }
}

// ---------------------------------------------------------------------------
// Rotary + layout transform: (b,n,h*d) -> (b,h,n,d); q scaled by QK_SCALE.
// ---------------------------------------------------------------------------
__global__ __launch_bounds__(256) void rotary_kernel(
    const float* __restrict__ qp, const float* __restrict__ kvp,
    const float* __restrict__ freqs)
{
    int i = blockIdx.x * blockDim.x + threadIdx.x;
    const int total = B_ * NH * SEQ * (HD / 2);
    if (i >= total) return;

    int p = i & (HD / 2 - 1);
    int r = i >> 6;
    int n = r & (SEQ - 1); r >>= 11;
    int h = r & (NH - 1);
    int b = r >> 4;
    int d0 = 2 * p;

    float f0 = freqs[n * HD + d0];
    float f1 = freqs[n * HD + d0 + 1];
    float c0 = cosf(f0), s0 = sinf(f0);
    float c1 = cosf(f1), s1 = sinf(f1);

    size_t qsrc = ((size_t)b * SEQ + n) * INNER + h * HD + d0;
    size_t ksrc = ((size_t)b * SEQ + n) * (2 * INNER) + h * HD + d0;
    size_t dst  = (((size_t)b * NH + h) * SEQ + n) * HD + d0;

    float q0 = qp[qsrc], q1 = qp[qsrc + 1];
    g_q[dst]     = (q0 * c0 - q1 * s0) * QK_SCALE;
    g_q[dst + 1] = (q1 * c1 + q0 * s1) * QK_SCALE;

    float k0 = kvp[ksrc], k1 = kvp[ksrc + 1];
    g_k[dst]     = k0 * c0 - k1 * s0;
    g_k[dst + 1] = k1 * c1 + k0 * s1;

    g_v[dst]     = kvp[ksrc + INNER];
    g_v[dst + 1] = kvp[ksrc + INNER + 1];
}

// ---------------------------------------------------------------------------
// Flash attention with tf32 mma. BM=64 (4 warps x 16 rows), BN=64, D=128.
// (unchanged from R4 — 884us, kept for clean attribution)
// ---------------------------------------------------------------------------
#define QSTR 132
#define KSTR 132
#define VSTR 136
#define PSTR 68

__global__ __launch_bounds__(128, 1) void flash_mma()
{
    extern __shared__ float smem[];
    float* sQ  = smem;                    // 64*QSTR
    float* sKV = sQ + 64 * QSTR;          // 64*VSTR (K: stride 132, V: stride 136)
    float* sP  = sKV + 64 * VSTR;         // 64*PSTR

    const int qt  = blockIdx.x;           // query tile
    const int bh  = blockIdx.y;           // b*NH + h
    const int tid = threadIdx.x;
    const int wid = tid >> 5, lane = tid & 31;
    const int gq = lane >> 2, tg = lane & 3;
    const int wrow = wid * 16;            // warp's query-row base in tile

    const float* Q  = g_q + ((size_t)bh * SEQ + (size_t)qt * 64) * HD;
    const float* Kp = g_k + (size_t)bh * SEQ * HD;
    const float* Vp = g_v + (size_t)bh * SEQ * HD;

    // load + round Q tile (64 x 128)
    for (int i = tid; i < 64 * 32; i += 128) {
        int r = i >> 5, q = i & 31;
        float4 v = *(const float4*)&Q[(size_t)r * HD + q * 4];
        sQ[r * QSTR + q * 4 + 0] = tf32_round(v.x);
        sQ[r * QSTR + q * 4 + 1] = tf32_round(v.y);
        sQ[r * QSTR + q * 4 + 2] = tf32_round(v.z);
        sQ[r * QSTR + q * 4 + 3] = tf32_round(v.w);
    }

    float oacc[16][4] = {};               // O: 16 rows x 128 cols per warp
    float m0 = -1e30f, m1 = -1e30f, l0 = 0.f, l1 = 0.f;
    __syncthreads();

    for (int j = 0; j < SEQ; j += 64) {
        // ---- K tile
        for (int i = tid; i < 64 * 32; i += 128) {
            int r = i >> 5, q = i & 31;
            float4 v = *(const float4*)&Kp[(size_t)(j + r) * HD + q * 4];
            sKV[r * KSTR + q * 4 + 0] = tf32_round(v.x);
            sKV[r * KSTR + q * 4 + 1] = tf32_round(v.y);
            sKV[r * KSTR + q * 4 + 2] = tf32_round(v.z);
            sKV[r * KSTR + q * 4 + 3] = tf32_round(v.w);
        }
        __syncthreads();

        // ---- S = Q K^T : 8 n-atoms x 16 k-atoms
        float sacc[8][4] = {};
        #pragma unroll
        for (int ka = 0; ka < 16; ka++) {
            const int kb = ka * 8;
            uint32_t a[4];
            a[0] = __float_as_uint(sQ[(wrow + gq    ) * QSTR + kb + tg    ]);
            a[1] = __float_as_uint(sQ[(wrow + gq + 8) * QSTR + kb + tg    ]);
            a[2] = __float_as_uint(sQ[(wrow + gq    ) * QSTR + kb + tg + 4]);
            a[3] = __float_as_uint(sQ[(wrow + gq + 8) * QSTR + kb + tg + 4]);
            #pragma unroll
            for (int na = 0; na < 8; na++) {
                uint32_t b0 = __float_as_uint(sKV[(na * 8 + gq) * KSTR + kb + tg    ]);
                uint32_t b1 = __float_as_uint(sKV[(na * 8 + gq) * KSTR + kb + tg + 4]);
                mma_tf32(sacc[na], a, b0, b1);
            }
        }

        // ---- online softmax (rows: r0 = wrow+gq, r1 = wrow+gq+8)
        float rmax0 = -1e30f, rmax1 = -1e30f;
        #pragma unroll
        for (int na = 0; na < 8; na++) {
            rmax0 = fmaxf(rmax0, fmaxf(sacc[na][0], sacc[na][1]));
            rmax1 = fmaxf(rmax1, fmaxf(sacc[na][2], sacc[na][3]));
        }
        rmax0 = fmaxf(rmax0, __shfl_xor_sync(0xffffffffu, rmax0, 1));
        rmax0 = fmaxf(rmax0, __shfl_xor_sync(0xffffffffu, rmax0, 2));
        rmax1 = fmaxf(rmax1, __shfl_xor_sync(0xffffffffu, rmax1, 1));
        rmax1 = fmaxf(rmax1, __shfl_xor_sync(0xffffffffu, rmax1, 2));

        float nm0 = fmaxf(m0, rmax0), nm1 = fmaxf(m1, rmax1);
        float al0 = __expf(m0 - nm0), al1 = __expf(m1 - nm1);
        float ls0 = 0.f, ls1 = 0.f;
        #pragma unroll
        for (int na = 0; na < 8; na++) {
            float p0 = __expf(sacc[na][0] - nm0);
            float p1 = __expf(sacc[na][1] - nm0);
            float p2 = __expf(sacc[na][2] - nm1);
            float p3 = __expf(sacc[na][3] - nm1);
            ls0 += p0 + p1; ls1 += p2 + p3;
            int c = na * 8 + 2 * tg;
            sP[(wrow + gq    ) * PSTR + c    ] = tf32_round(p0);
            sP[(wrow + gq    ) * PSTR + c + 1] = tf32_round(p1);
            sP[(wrow + gq + 8) * PSTR + c    ] = tf32_round(p2);
            sP[(wrow + gq + 8) * PSTR + c + 1] = tf32_round(p3);
        }
        ls0 += __shfl_xor_sync(0xffffffffu, ls0, 1);
        ls0 += __shfl_xor_sync(0xffffffffu, ls0, 2);
        ls1 += __shfl_xor_sync(0xffffffffu, ls1, 1);
        ls1 += __shfl_xor_sync(0xffffffffu, ls1, 2);
        l0 = l0 * al0 + ls0;
        l1 = l1 * al1 + ls1;
        m0 = nm0; m1 = nm1;

        #pragma unroll
        for (int na = 0; na < 16; na++) {
            oacc[na][0] *= al0; oacc[na][1] *= al0;
            oacc[na][2] *= al1; oacc[na][3] *= al1;
        }
        __syncthreads();   // P written; all K-reads done

        // ---- V tile (overwrites K buffer, stride VSTR)
        for (int i = tid; i < 64 * 32; i += 128) {
            int r = i >> 5, q = i & 31;
            float4 v = *(const float4*)&Vp[(size_t)(j + r) * HD + q * 4];
            sKV[r * VSTR + q * 4 + 0] = tf32_round(v.x);
            sKV[r * VSTR + q * 4 + 1] = tf32_round(v.y);
            sKV[r * VSTR + q * 4 + 2] = tf32_round(v.z);
            sKV[r * VSTR + q * 4 + 3] = tf32_round(v.w);
        }
        __syncthreads();

        // ---- O += P @ V : 8 k-atoms x 16 n-atoms
        #pragma unroll
        for (int ka = 0; ka < 8; ka++) {
            const int kb = ka * 8;
            uint32_t a[4];
            a[0] = __float_as_uint(sP[(wrow + gq    ) * PSTR + kb + tg    ]);
            a[1] = __float_as_uint(sP[(wrow + gq + 8) * PSTR + kb + tg    ]);
            a[2] = __float_as_uint(sP[(wrow + gq    ) * PSTR + kb + tg + 4]);
            a[3] = __float_as_uint(sP[(wrow + gq + 8) * PSTR + kb + tg + 4]);
            #pragma unroll
            for (int na = 0; na < 16; na++) {
                uint32_t b0 = __float_as_uint(sKV[(kb + tg    ) * VSTR + na * 8 + gq]);
                uint32_t b1 = __float_as_uint(sKV[(kb + tg + 4) * VSTR + na * 8 + gq]);
                mma_tf32(oacc[na], a, b0, b1);
            }
        }
        __syncthreads();   // before next K tile overwrites sKV
    }

    // ---- epilogue: normalize, write to (b,n,h*d)
    const int b = bh >> 4, h = bh & 15;
    const float inv0 = 1.f / l0, inv1 = 1.f / l1;
    const int r0 = qt * 64 + wrow + gq;
    #pragma unroll
    for (int na = 0; na < 16; na++) {
        int c = h * HD + na * 8 + 2 * tg;
        size_t base0 = ((size_t)b * SEQ + r0) * INNER + c;
        size_t base1 = ((size_t)b * SEQ + r0 + 8) * INNER + c;
        g_ao[base0]     = oacc[na][0] * inv0;
        g_ao[base0 + 1] = oacc[na][1] * inv0;
        g_ao[base1]     = oacc[na][2] * inv1;
        g_ao[base1 + 1] = oacc[na][3] * inv1;
    }
}

// ---------------------------------------------------------------------------
extern "C" void kernel_launch(void* const* d_in, const int* in_sizes, int n_in,
                              void* d_out, int out_size)
{
    const float* x   = (const float*)d_in[0];
    const float* rot = (const float*)d_in[1];
    const float* Wq  = (const float*)d_in[2];
    const float* Wkv = (const float*)d_in[3];
    const float* Wo  = (const float*)d_in[4];
    const float* bo  = (const float*)d_in[5];
    float* out = (float*)d_out;

    float *qproj, *kv, *ao;
    cudaGetSymbolAddress((void**)&qproj, g_qproj);
    cudaGetSymbolAddress((void**)&kv,   g_kv);
    cudaGetSymbolAddress((void**)&ao,   g_ao);

    const int M = B_ * SEQ;   // 4096

    // 1) Q = x @ Wq
    gemm_bf16<<<dim3(INNER / 128, M / 128), 256>>>(x, Wq, qproj, M, INNER, DIM, nullptr);
    // 2) KV = x @ Wkv
    gemm_bf16<<<dim3(2 * INNER / 128, M / 128), 256>>>(x, Wkv, kv, M, 2 * INNER, DIM, nullptr);
    // 3) rotary + layout
    {
        int total = B_ * NH * SEQ * (HD / 2);
        rotary_kernel<<<total / 256, 256>>>(qproj, kv, rot);
    }
    // 4) flash attention (tf32 mma)
    {
        size_t smemb = (size_t)(64 * QSTR + 64 * VSTR + 64 * PSTR) * sizeof(float);
        cudaFuncSetAttribute(flash_mma, cudaFuncAttributeMaxDynamicSharedMemorySize, (int)smemb);
        flash_mma<<<dim3(SEQ / 64, B_ * NH), 128, smemb>>>();
    }
    // 5) out = ao @ Wo + bo
    gemm_bf16<<<dim3(DIM / 128, M / 128), 256>>>(ao, Wo, out, M, DIM, INNER, bo);
}

// round 7
// speedup vs baseline: 3.2040x; 1.2733x over previous
#include <cuda_runtime.h>
#include <cuda_bf16.h>
#include <cstdint>

// Problem constants
#define B_    2
#define SEQ   2048
#define DIM   2048
#define NH    16
#define HD    128
#define INNER 2048           // NH*HD
#define QK_SCALE 0.08838834764831845f   // 128^-0.5

// ---------------- scratch (device globals; no allocations allowed) ----------
__device__ float g_qproj[(size_t)B_ * SEQ * INNER];
__device__ float g_kv  [(size_t)B_ * SEQ * 2 * INNER];
__device__ float g_q   [(size_t)B_ * NH * SEQ * HD];   // (b,h,n,d) rotated+scaled
__device__ float g_k   [(size_t)B_ * NH * SEQ * HD];
__device__ float g_v   [(size_t)B_ * NH * SEQ * HD];

// pre-split bf16 hi/lo operands
__device__ __nv_bfloat16 g_xh [(size_t)4096 * 2048];
__device__ __nv_bfloat16 g_xl [(size_t)4096 * 2048];
__device__ __nv_bfloat16 g_wqh[(size_t)2048 * 2048];   // [N,K] transposed
__device__ __nv_bfloat16 g_wql[(size_t)2048 * 2048];
__device__ __nv_bfloat16 g_wkvh[(size_t)4096 * 2048];  // [N,K]
__device__ __nv_bfloat16 g_wkvl[(size_t)4096 * 2048];
__device__ __nv_bfloat16 g_woh[(size_t)2048 * 2048];   // [N,K]
__device__ __nv_bfloat16 g_wol[(size_t)2048 * 2048];
__device__ __nv_bfloat16 g_aoh[(size_t)4096 * 2048];   // flash writes these
__device__ __nv_bfloat16 g_aol[(size_t)4096 * 2048];

// ---------------------------------------------------------------------------
// tf32 helpers (flash kernel)
// ---------------------------------------------------------------------------
__device__ __forceinline__ uint32_t f2tf32(float f) {
    uint32_t u;
    asm("cvt.rna.tf32.f32 %0, %1;" : "=r"(u) : "f"(f));
    return u;
}
__device__ __forceinline__ float tf32_round(float f) {
    return __uint_as_float(f2tf32(f));
}
__device__ __forceinline__ void mma_tf32(float* d, const uint32_t* a,
                                         uint32_t b0, uint32_t b1) {
    asm volatile(
        "mma.sync.aligned.m16n8k8.row.col.f32.tf32.tf32.f32 "
        "{%0,%1,%2,%3}, {%4,%5,%6,%7}, {%8,%9}, {%0,%1,%2,%3};"
        : "+f"(d[0]), "+f"(d[1]), "+f"(d[2]), "+f"(d[3])
        : "r"(a[0]), "r"(a[1]), "r"(a[2]), "r"(a[3]), "r"(b0), "r"(b1));
}

// ---------------------------------------------------------------------------
// bf16 helpers (GEMM)
// ---------------------------------------------------------------------------
__device__ __forceinline__ void mma_bf16(float* d, const uint32_t* a,
                                         uint32_t b0, uint32_t b1) {
    asm volatile(
        "mma.sync.aligned.m16n8k16.row.col.f32.bf16.bf16.f32 "
        "{%0,%1,%2,%3}, {%4,%5,%6,%7}, {%8,%9}, {%0,%1,%2,%3};"
        : "+f"(d[0]), "+f"(d[1]), "+f"(d[2]), "+f"(d[3])
        : "r"(a[0]), "r"(a[1]), "r"(a[2]), "r"(a[3]), "r"(b0), "r"(b1));
}
__device__ __forceinline__ void ldsm4(uint32_t* r, uint32_t saddr) {
    asm volatile("ldmatrix.sync.aligned.m8n8.x4.shared.b16 {%0,%1,%2,%3}, [%4];"
        : "=r"(r[0]), "=r"(r[1]), "=r"(r[2]), "=r"(r[3]) : "r"(saddr));
}
__device__ __forceinline__ void cpasync16(uint32_t saddr, const void* g) {
    asm volatile("cp.async.cg.shared.global [%0], [%1], 16;" :: "r"(saddr), "l"(g));
}

// ---------------------------------------------------------------------------
// split kernel: fp32 -> bf16 hi + bf16 lo (elementwise), 4 elems/thread
// ---------------------------------------------------------------------------
__global__ __launch_bounds__(256) void splitHL(
    const float4* __restrict__ src,
    __nv_bfloat16* __restrict__ dh, __nv_bfloat16* __restrict__ dl, int n4)
{
    int i = blockIdx.x * 256 + threadIdx.x;
    if (i >= n4) return;
    float4 v = src[i];
    float vv[4] = {v.x, v.y, v.z, v.w};
    int base = i * 4;
    #pragma unroll
    for (int j = 0; j < 4; j++) {
        __nv_bfloat16 h = __float2bfloat16(vv[j]);
        dh[base + j] = h;
        dl[base + j] = __float2bfloat16(vv[j] - __bfloat162float(h));
    }
}

// ---------------------------------------------------------------------------
// transpose + split: src [K,N] fp32 -> dh/dl [N,K] bf16
// ---------------------------------------------------------------------------
__global__ __launch_bounds__(256) void convT(
    const float* __restrict__ src,
    __nv_bfloat16* __restrict__ dh, __nv_bfloat16* __restrict__ dl,
    int K, int N)
{
    __shared__ float t[32][33];
    int n0 = blockIdx.x * 32, k0 = blockIdx.y * 32;
    int tx = threadIdx.x & 31, ty = threadIdx.x >> 5;
    #pragma unroll
    for (int r = ty; r < 32; r += 8)
        t[r][tx] = src[(size_t)(k0 + r) * N + n0 + tx];
    __syncthreads();
    #pragma unroll
    for (int r = ty; r < 32; r += 8) {
        float v = t[tx][r];
        __nv_bfloat16 h = __float2bfloat16(v);
        size_t o = (size_t)(n0 + r) * K + k0 + tx;
        dh[o] = h;
        dl[o] = __float2bfloat16(v - __bfloat162float(h));
    }
}

// ---------------------------------------------------------------------------
// 3xBF16 GEMM with PRE-SPLIT operands.
// A: [M,K] bf16 hi/lo (row-major).  B: [N,K] bf16 hi/lo (k-contiguous).
// BM=BN=128, BK=32, 256 threads, 8 warps (warp tile 64m x 32n).
// cp.async double-buffered staging; ldmatrix.x4 fragment loads.
// smem per array: [2 bufs][128 rows][20 words] (16 data words = 32 bf16 + pad)
// ---------------------------------------------------------------------------
#define GW   20                         // words per row (80B, 16B-aligned)
#define GBUF (128 * GW)                 // 2560 words per buffer
#define GARR (2 * GBUF)                 // 5120 words per array
#define GSMEM_BYTES (4 * GARR * 4)      // 81920 B

__global__ __launch_bounds__(256) void gemm_bf16p(
    const __nv_bfloat16* __restrict__ Ah, const __nv_bfloat16* __restrict__ Al,
    const __nv_bfloat16* __restrict__ Bh, const __nv_bfloat16* __restrict__ Bl,
    float* __restrict__ C, int M, int N, int K,
    const float* __restrict__ bias)
{
    extern __shared__ uint32_t smp[];
    const uint32_t sbase = (uint32_t)__cvta_generic_to_shared(smp);
    // array word bases
    const uint32_t bAh = 0, bAl = GARR, bBh = 2 * GARR, bBl = 3 * GARR;

    const int bm = blockIdx.y * 128;
    const int bn = blockIdx.x * 128;
    const int tid = threadIdx.x;
    const int wid = tid >> 5, lane = tid & 31;
    const int wm = (wid & 1) * 64;
    const int wn = (wid >> 1) * 32;
    const int gq = lane >> 2, tg = lane & 3;

    // ldmatrix per-lane row/word offsets
    const int arow = (lane & 7) | (lane & 8);            // A: matrices 0/1 rows 0-15
    const int awrd = (lane & 16) ? 4 : 0;                //    matrices 2/3 k-high
    const int brow = (lane & 7) | ((lane & 16) >> 1);    // B: matrices 2/3 rows +8
    const int bwrd = (lane & 8) ? 4 : 0;                 //    matrices 1/3 k-high

    // staging mapping: thread -> (row, half)
    const int srow = tid >> 1, shalf = tid & 1;
    const __nv_bfloat16* gah = Ah + (size_t)(bm + srow) * K + shalf * 16;
    const __nv_bfloat16* gal = Al + (size_t)(bm + srow) * K + shalf * 16;
    const __nv_bfloat16* gbh = Bh + (size_t)(bn + srow) * K + shalf * 16;
    const __nv_bfloat16* gbl = Bl + (size_t)(bn + srow) * K + shalf * 16;
    const uint32_t swoff = (srow * GW + shalf * 8) * 4;  // byte offset within buffer

    float acc[4][4][4] = {};

    auto issue_tile = [&](int t, int b) {
        const int koff = t * 32;
        const uint32_t bb = b * GBUF * 4;
        cpasync16(sbase + bAh * 4 + bb + swoff,      gah + koff);
        cpasync16(sbase + bAh * 4 + bb + swoff + 16, gah + koff + 8);
        cpasync16(sbase + bAl * 4 + bb + swoff,      gal + koff);
        cpasync16(sbase + bAl * 4 + bb + swoff + 16, gal + koff + 8);
        cpasync16(sbase + bBh * 4 + bb + swoff,      gbh + koff);
        cpasync16(sbase + bBh * 4 + bb + swoff + 16, gbh + koff + 8);
        cpasync16(sbase + bBl * 4 + bb + swoff,      gbl + koff);
        cpasync16(sbase + bBl * 4 + bb + swoff + 16, gbl + koff + 8);
        asm volatile("cp.async.commit_group;" ::: "memory");
    };

    const int NT = K / 32;
    issue_tile(0, 0);

    int buf = 0;
    for (int t = 0; t < NT; t++) {
        if (t + 1 < NT) {
            issue_tile(t + 1, buf ^ 1);
            asm volatile("cp.async.wait_group 1;" ::: "memory");
        } else {
            asm volatile("cp.async.wait_group 0;" ::: "memory");
        }
        __syncthreads();

        const uint32_t bb = buf * GBUF * 4;
        #pragma unroll
        for (int kk = 0; kk < 2; kk++) {
            const int kbw = kk * 8;
            uint32_t ah[4][4], al[4][4];
            #pragma unroll
            for (int ma = 0; ma < 4; ma++) {
                uint32_t ro = ((wm + ma * 16 + arow) * GW + kbw + awrd) * 4;
                ldsm4(ah[ma], sbase + bAh * 4 + bb + ro);
                ldsm4(al[ma], sbase + bAl * 4 + bb + ro);
            }
            uint32_t bh[2][4], bl[2][4];
            #pragma unroll
            for (int np = 0; np < 2; np++) {
                uint32_t ro = ((wn + np * 16 + brow) * GW + kbw + bwrd) * 4;
                ldsm4(bh[np], sbase + bBh * 4 + bb + ro);
                ldsm4(bl[np], sbase + bBl * 4 + bb + ro);
            }
            #pragma unroll
            for (int na = 0; na < 4; na++) {
                uint32_t bh0 = bh[na >> 1][(na & 1) * 2], bh1 = bh[na >> 1][(na & 1) * 2 + 1];
                uint32_t bl0 = bl[na >> 1][(na & 1) * 2], bl1 = bl[na >> 1][(na & 1) * 2 + 1];
                #pragma unroll
                for (int ma = 0; ma < 4; ma++) {
                    mma_bf16(acc[ma][na], ah[ma], bh0, bh1);
                    mma_bf16(acc[ma][na], ah[ma], bl0, bl1);
                    mma_bf16(acc[ma][na], al[ma], bh0, bh1);
                }
            }
        }
        __syncthreads();
        buf ^= 1;
    }

    // ---- epilogue
    #pragma unroll
    for (int ma = 0; ma < 4; ma++) {
        int r0 = bm + wm + ma * 16 + gq;
        #pragma unroll
        for (int na = 0; na < 4; na++) {
            int c = bn + wn + na * 8 + 2 * tg;
            float b0 = bias ? bias[c] : 0.f;
            float b1 = bias ? bias[c + 1] : 0.f;
            C[(size_t)r0 * N + c]           = acc[ma][na][0] + b0;
            C[(size_t)r0 * N + c + 1]       = acc[ma][na][1] + b1;
            C[(size_t)(r0 + 8) * N + c]     = acc[ma][na][2] + b0;
            C[(size_t)(r0 + 8) * N + c + 1] = acc[ma][na][3] + b1;
        }
    }
}

// ---------------------------------------------------------------------------
// Rotary + layout transform: (b,n,h*d) -> (b,h,n,d); q scaled by QK_SCALE.
// ---------------------------------------------------------------------------
__global__ __launch_bounds__(256) void rotary_kernel(
    const float* __restrict__ qp, const float* __restrict__ kvp,
    const float* __restrict__ freqs)
{
    int i = blockIdx.x * blockDim.x + threadIdx.x;
    const int total = B_ * NH * SEQ * (HD / 2);
    if (i >= total) return;

    int p = i & (HD / 2 - 1);
    int r = i >> 6;
    int n = r & (SEQ - 1); r >>= 11;
    int h = r & (NH - 1);
    int b = r >> 4;
    int d0 = 2 * p;

    float f0 = freqs[n * HD + d0];
    float f1 = freqs[n * HD + d0 + 1];
    float c0 = cosf(f0), s0 = sinf(f0);
    float c1 = cosf(f1), s1 = sinf(f1);

    size_t qsrc = ((size_t)b * SEQ + n) * INNER + h * HD + d0;
    size_t ksrc = ((size_t)b * SEQ + n) * (2 * INNER) + h * HD + d0;
    size_t dst  = (((size_t)b * NH + h) * SEQ + n) * HD + d0;

    float q0 = qp[qsrc], q1 = qp[qsrc + 1];
    g_q[dst]     = (q0 * c0 - q1 * s0) * QK_SCALE;
    g_q[dst + 1] = (q1 * c1 + q0 * s1) * QK_SCALE;

    float k0 = kvp[ksrc], k1 = kvp[ksrc + 1];
    g_k[dst]     = k0 * c0 - k1 * s0;
    g_k[dst + 1] = k1 * c1 + k0 * s1;

    g_v[dst]     = kvp[ksrc + INNER];
    g_v[dst + 1] = kvp[ksrc + INNER + 1];
}

// ---------------------------------------------------------------------------
// Flash attention with tf32 mma (unchanged math from R4/R6).
// Epilogue now writes bf16 hi/lo ao directly (feeds pre-split Wo GEMM).
// ---------------------------------------------------------------------------
#define QSTR 132
#define KSTR 132
#define VSTR 136
#define PSTR 68

__global__ __launch_bounds__(128, 1) void flash_mma()
{
    extern __shared__ float smem[];
    float* sQ  = smem;
    float* sKV = sQ + 64 * QSTR;
    float* sP  = sKV + 64 * VSTR;

    const int qt  = blockIdx.x;
    const int bh  = blockIdx.y;
    const int tid = threadIdx.x;
    const int wid = tid >> 5, lane = tid & 31;
    const int gq = lane >> 2, tg = lane & 3;
    const int wrow = wid * 16;

    const float* Q  = g_q + ((size_t)bh * SEQ + (size_t)qt * 64) * HD;
    const float* Kp = g_k + (size_t)bh * SEQ * HD;
    const float* Vp = g_v + (size_t)bh * SEQ * HD;

    for (int i = tid; i < 64 * 32; i += 128) {
        int r = i >> 5, q = i & 31;
        float4 v = *(const float4*)&Q[(size_t)r * HD + q * 4];
        sQ[r * QSTR + q * 4 + 0] = tf32_round(v.x);
        sQ[r * QSTR + q * 4 + 1] = tf32_round(v.y);
        sQ[r * QSTR + q * 4 + 2] = tf32_round(v.z);
        sQ[r * QSTR + q * 4 + 3] = tf32_round(v.w);
    }

    float oacc[16][4] = {};
    float m0 = -1e30f, m1 = -1e30f, l0 = 0.f, l1 = 0.f;
    __syncthreads();

    for (int j = 0; j < SEQ; j += 64) {
        for (int i = tid; i < 64 * 32; i += 128) {
            int r = i >> 5, q = i & 31;
            float4 v = *(const float4*)&Kp[(size_t)(j + r) * HD + q * 4];
            sKV[r * KSTR + q * 4 + 0] = tf32_round(v.x);
            sKV[r * KSTR + q * 4 + 1] = tf32_round(v.y);
            sKV[r * KSTR + q * 4 + 2] = tf32_round(v.z);
            sKV[r * KSTR + q * 4 + 3] = tf32_round(v.w);
        }
        __syncthreads();

        float sacc[8][4] = {};
        #pragma unroll
        for (int ka = 0; ka < 16; ka++) {
            const int kb = ka * 8;
            uint32_t a[4];
            a[0] = __float_as_uint(sQ[(wrow + gq    ) * QSTR + kb + tg    ]);
            a[1] = __float_as_uint(sQ[(wrow + gq + 8) * QSTR + kb + tg    ]);
            a[2] = __float_as_uint(sQ[(wrow + gq    ) * QSTR + kb + tg + 4]);
            a[3] = __float_as_uint(sQ[(wrow + gq + 8) * QSTR + kb + tg + 4]);
            #pragma unroll
            for (int na = 0; na < 8; na++) {
                uint32_t b0 = __float_as_uint(sKV[(na * 8 + gq) * KSTR + kb + tg    ]);
                uint32_t b1 = __float_as_uint(sKV[(na * 8 + gq) * KSTR + kb + tg + 4]);
                mma_tf32(sacc[na], a, b0, b1);
            }
        }

        float rmax0 = -1e30f, rmax1 = -1e30f;
        #pragma unroll
        for (int na = 0; na < 8; na++) {
            rmax0 = fmaxf(rmax0, fmaxf(sacc[na][0], sacc[na][1]));
            rmax1 = fmaxf(rmax1, fmaxf(sacc[na][2], sacc[na][3]));
        }
        rmax0 = fmaxf(rmax0, __shfl_xor_sync(0xffffffffu, rmax0, 1));
        rmax0 = fmaxf(rmax0, __shfl_xor_sync(0xffffffffu, rmax0, 2));
        rmax1 = fmaxf(rmax1, __shfl_xor_sync(0xffffffffu, rmax1, 1));
        rmax1 = fmaxf(rmax1, __shfl_xor_sync(0xffffffffu, rmax1, 2));

        float nm0 = fmaxf(m0, rmax0), nm1 = fmaxf(m1, rmax1);
        float al0 = __expf(m0 - nm0), al1 = __expf(m1 - nm1);
        float ls0 = 0.f, ls1 = 0.f;
        #pragma unroll
        for (int na = 0; na < 8; na++) {
            float p0 = __expf(sacc[na][0] - nm0);
            float p1 = __expf(sacc[na][1] - nm0);
            float p2 = __expf(sacc[na][2] - nm1);
            float p3 = __expf(sacc[na][3] - nm1);
            ls0 += p0 + p1; ls1 += p2 + p3;
            int c = na * 8 + 2 * tg;
            sP[(wrow + gq    ) * PSTR + c    ] = tf32_round(p0);
            sP[(wrow + gq    ) * PSTR + c + 1] = tf32_round(p1);
            sP[(wrow + gq + 8) * PSTR + c    ] = tf32_round(p2);
            sP[(wrow + gq + 8) * PSTR + c + 1] = tf32_round(p3);
        }
        ls0 += __shfl_xor_sync(0xffffffffu, ls0, 1);
        ls0 += __shfl_xor_sync(0xffffffffu, ls0, 2);
        ls1 += __shfl_xor_sync(0xffffffffu, ls1, 1);
        ls1 += __shfl_xor_sync(0xffffffffu, ls1, 2);
        l0 = l0 * al0 + ls0;
        l1 = l1 * al1 + ls1;
        m0 = nm0; m1 = nm1;

        #pragma unroll
        for (int na = 0; na < 16; na++) {
            oacc[na][0] *= al0; oacc[na][1] *= al0;
            oacc[na][2] *= al1; oacc[na][3] *= al1;
        }
        __syncthreads();

        for (int i = tid; i < 64 * 32; i += 128) {
            int r = i >> 5, q = i & 31;
            float4 v = *(const float4*)&Vp[(size_t)(j + r) * HD + q * 4];
            sKV[r * VSTR + q * 4 + 0] = tf32_round(v.x);
            sKV[r * VSTR + q * 4 + 1] = tf32_round(v.y);
            sKV[r * VSTR + q * 4 + 2] = tf32_round(v.z);
            sKV[r * VSTR + q * 4 + 3] = tf32_round(v.w);
        }
        __syncthreads();

        #pragma unroll
        for (int ka = 0; ka < 8; ka++) {
            const int kb = ka * 8;
            uint32_t a[4];
            a[0] = __float_as_uint(sP[(wrow + gq    ) * PSTR + kb + tg    ]);
            a[1] = __float_as_uint(sP[(wrow + gq + 8) * PSTR + kb + tg    ]);
            a[2] = __float_as_uint(sP[(wrow + gq    ) * PSTR + kb + tg + 4]);
            a[3] = __float_as_uint(sP[(wrow + gq + 8) * PSTR + kb + tg + 4]);
            #pragma unroll
            for (int na = 0; na < 16; na++) {
                uint32_t b0 = __float_as_uint(sKV[(kb + tg    ) * VSTR + na * 8 + gq]);
                uint32_t b1 = __float_as_uint(sKV[(kb + tg + 4) * VSTR + na * 8 + gq]);
                mma_tf32(oacc[na], a, b0, b1);
            }
        }
        __syncthreads();
    }

    // ---- epilogue: normalize, write bf16 hi/lo to (b,n,h*d)
    const int b = bh >> 4, h = bh & 15;
    const float inv0 = 1.f / l0, inv1 = 1.f / l1;
    const int r0 = qt * 64 + wrow + gq;
    #pragma unroll
    for (int na = 0; na < 16; na++) {
        int c = h * HD + na * 8 + 2 * tg;
        size_t base0 = ((size_t)b * SEQ + r0) * INNER + c;
        size_t base1 = ((size_t)b * SEQ + r0 + 8) * INNER + c;
        float v00 = oacc[na][0] * inv0, v01 = oacc[na][1] * inv0;
        float v10 = oacc[na][2] * inv1, v11 = oacc[na][3] * inv1;
        __nv_bfloat16 hh;
        hh = __float2bfloat16(v00); g_aoh[base0]     = hh; g_aol[base0]     = __float2bfloat16(v00 - __bfloat162float(hh));
        hh = __float2bfloat16(v01); g_aoh[base0 + 1] = hh; g_aol[base0 + 1] = __float2bfloat16(v01 - __bfloat162float(hh));
        hh = __float2bfloat16(v10); g_aoh[base1]     = hh; g_aol[base1]     = __float2bfloat16(v10 - __bfloat162float(hh));
        hh = __float2bfloat16(v11); g_aoh[base1 + 1] = hh; g_aol[base1 + 1] = __float2bfloat16(v11 - __bfloat162float(hh));
    }
}

// ---------------------------------------------------------------------------
extern "C" void kernel_launch(void* const* d_in, const int* in_sizes, int n_in,
                              void* d_out, int out_size)
{
    const float* x   = (const float*)d_in[0];
    const float* rot = (const float*)d_in[1];
    const float* Wq  = (const float*)d_in[2];
    const float* Wkv = (const float*)d_in[3];
    const float* Wo  = (const float*)d_in[4];
    const float* bo  = (const float*)d_in[5];
    float* out = (float*)d_out;

    float *qproj, *kv;
    cudaGetSymbolAddress((void**)&qproj, g_qproj);
    cudaGetSymbolAddress((void**)&kv,   g_kv);
    __nv_bfloat16 *xh, *xl, *wqh, *wql, *wkvh, *wkvl, *woh, *wol, *aoh, *aol;
    cudaGetSymbolAddress((void**)&xh,  g_xh);   cudaGetSymbolAddress((void**)&xl,  g_xl);
    cudaGetSymbolAddress((void**)&wqh, g_wqh);  cudaGetSymbolAddress((void**)&wql, g_wql);
    cudaGetSymbolAddress((void**)&wkvh, g_wkvh); cudaGetSymbolAddress((void**)&wkvl, g_wkvl);
    cudaGetSymbolAddress((void**)&woh, g_woh);  cudaGetSymbolAddress((void**)&wol, g_wol);
    cudaGetSymbolAddress((void**)&aoh, g_aoh);  cudaGetSymbolAddress((void**)&aol, g_aol);

    const int M = B_ * SEQ;   // 4096

    // 0) pre-split operands (x elementwise; weights transposed to [N,K])
    {
        int n4 = M * DIM / 4;
        splitHL<<<(n4 + 255) / 256, 256>>>((const float4*)x, xh, xl, n4);
        convT<<<dim3(INNER / 32,     DIM / 32), 256>>>(Wq,  wqh,  wql,  DIM,   INNER);
        convT<<<dim3(2 * INNER / 32, DIM / 32), 256>>>(Wkv, wkvh, wkvl, DIM,   2 * INNER);
        convT<<<dim3(DIM / 32,     INNER / 32), 256>>>(Wo,  woh,  wol,  INNER, DIM);
    }

    cudaFuncSetAttribute(gemm_bf16p, cudaFuncAttributeMaxDynamicSharedMemorySize, GSMEM_BYTES);

    // 1) Q = x @ Wq
    gemm_bf16p<<<dim3(INNER / 128, M / 128), 256, GSMEM_BYTES>>>(
        xh, xl, wqh, wql, qproj, M, INNER, DIM, nullptr);
    // 2) KV = x @ Wkv
    gemm_bf16p<<<dim3(2 * INNER / 128, M / 128), 256, GSMEM_BYTES>>>(
        xh, xl, wkvh, wkvl, kv, M, 2 * INNER, DIM, nullptr);
    // 3) rotary + layout
    {
        int total = B_ * NH * SEQ * (HD / 2);
        rotary_kernel<<<total / 256, 256>>>(qproj, kv, rot);
    }
    // 4) flash attention (tf32 mma) -> writes aoh/aol
    {
        size_t smemb = (size_t)(64 * QSTR + 64 * VSTR + 64 * PSTR) * sizeof(float);
        cudaFuncSetAttribute(flash_mma, cudaFuncAttributeMaxDynamicSharedMemorySize, (int)smemb);
        flash_mma<<<dim3(SEQ / 64, B_ * NH), 128, smemb>>>();
    }
    // 5) out = ao @ Wo + bo
    gemm_bf16p<<<dim3(DIM / 128, M / 128), 256, GSMEM_BYTES>>>(
        aoh, aol, woh, wol, out, M, DIM, INNER, bo);
}

// round 13
// speedup vs baseline: 3.5653x; 1.1128x over previous
#include <cuda_runtime.h>
#include <cuda_bf16.h>
#include <cstdint>

// Problem constants
#define B_    2
#define SEQ   2048
#define DIM   2048
#define NH    16
#define HD    128
#define INNER 2048           // NH*HD
#define QK_SCALE 0.08838834764831845f   // 128^-0.5

// ---------------- scratch (device globals; no allocations allowed) ----------
__device__ float g_qproj[(size_t)B_ * SEQ * INNER];
__device__ float g_kv  [(size_t)B_ * SEQ * 2 * INNER];
__device__ float g_q   [(size_t)B_ * NH * SEQ * HD];   // (b,h,n,d) rotated+scaled, tf32-rounded
__device__ float g_k   [(size_t)B_ * NH * SEQ * HD];   // tf32-rounded
__device__ float g_v   [(size_t)B_ * NH * SEQ * HD];   // tf32-rounded

// pre-split bf16 hi/lo operands
__device__ __nv_bfloat16 g_xh [(size_t)4096 * 2048];
__device__ __nv_bfloat16 g_xl [(size_t)4096 * 2048];
__device__ __nv_bfloat16 g_wqh[(size_t)2048 * 2048];   // [N,K] transposed
__device__ __nv_bfloat16 g_wql[(size_t)2048 * 2048];
__device__ __nv_bfloat16 g_wkvh[(size_t)4096 * 2048];  // [N,K]
__device__ __nv_bfloat16 g_wkvl[(size_t)4096 * 2048];
__device__ __nv_bfloat16 g_woh[(size_t)2048 * 2048];   // [N,K]
__device__ __nv_bfloat16 g_wol[(size_t)2048 * 2048];
__device__ __nv_bfloat16 g_aoh[(size_t)4096 * 2048];   // flash writes these
__device__ __nv_bfloat16 g_aol[(size_t)4096 * 2048];

// ---------------------------------------------------------------------------
// tf32 helpers
// ---------------------------------------------------------------------------
__device__ __forceinline__ uint32_t f2tf32(float f) {
    uint32_t u;
    asm("cvt.rna.tf32.f32 %0, %1;" : "=r"(u) : "f"(f));
    return u;
}
__device__ __forceinline__ float tf32_round(float f) {
    return __uint_as_float(f2tf32(f));
}
__device__ __forceinline__ void mma_tf32(float* d, const uint32_t* a,
                                         uint32_t b0, uint32_t b1) {
    asm volatile(
        "mma.sync.aligned.m16n8k8.row.col.f32.tf32.tf32.f32 "
        "{%0,%1,%2,%3}, {%4,%5,%6,%7}, {%8,%9}, {%0,%1,%2,%3};"
        : "+f"(d[0]), "+f"(d[1]), "+f"(d[2]), "+f"(d[3])
        : "r"(a[0]), "r"(a[1]), "r"(a[2]), "r"(a[3]), "r"(b0), "r"(b1));
}

// ---------------------------------------------------------------------------
// bf16 helpers (GEMM)
// ---------------------------------------------------------------------------
__device__ __forceinline__ void mma_bf16(float* d, const uint32_t* a,
                                         uint32_t b0, uint32_t b1) {
    asm volatile(
        "mma.sync.aligned.m16n8k16.row.col.f32.bf16.bf16.f32 "
        "{%0,%1,%2,%3}, {%4,%5,%6,%7}, {%8,%9}, {%0,%1,%2,%3};"
        : "+f"(d[0]), "+f"(d[1]), "+f"(d[2]), "+f"(d[3])
        : "r"(a[0]), "r"(a[1]), "r"(a[2]), "r"(a[3]), "r"(b0), "r"(b1));
}
__device__ __forceinline__ void ldsm4(uint32_t* r, uint32_t saddr) {
    asm volatile("ldmatrix.sync.aligned.m8n8.x4.shared.b16 {%0,%1,%2,%3}, [%4];"
        : "=r"(r[0]), "=r"(r[1]), "=r"(r[2]), "=r"(r[3]) : "r"(saddr));
}
__device__ __forceinline__ void cpasync16(uint32_t saddr, const void* g) {
    asm volatile("cp.async.cg.shared.global [%0], [%1], 16;" :: "r"(saddr), "l"(g));
}

// ---------------------------------------------------------------------------
// split kernel: fp32 -> bf16 hi + bf16 lo (elementwise), 4 elems/thread
// ---------------------------------------------------------------------------
__global__ __launch_bounds__(256) void splitHL(
    const float4* __restrict__ src,
    __nv_bfloat16* __restrict__ dh, __nv_bfloat16* __restrict__ dl, int n4)
{
    int i = blockIdx.x * 256 + threadIdx.x;
    if (i >= n4) return;
    float4 v = src[i];
    float vv[4] = {v.x, v.y, v.z, v.w};
    int base = i * 4;
    #pragma unroll
    for (int j = 0; j < 4; j++) {
        __nv_bfloat16 h = __float2bfloat16(vv[j]);
        dh[base + j] = h;
        dl[base + j] = __float2bfloat16(vv[j] - __bfloat162float(h));
    }
}

// ---------------------------------------------------------------------------
// transpose + split: src [K,N] fp32 -> dh/dl [N,K] bf16
// ---------------------------------------------------------------------------
__global__ __launch_bounds__(256) void convT(
    const float* __restrict__ src,
    __nv_bfloat16* __restrict__ dh, __nv_bfloat16* __restrict__ dl,
    int K, int N)
{
    __shared__ float t[32][33];
    int n0 = blockIdx.x * 32, k0 = blockIdx.y * 32;
    int tx = threadIdx.x & 31, ty = threadIdx.x >> 5;
    #pragma unroll
    for (int r = ty; r < 32; r += 8)
        t[r][tx] = src[(size_t)(k0 + r) * N + n0 + tx];
    __syncthreads();
    #pragma unroll
    for (int r = ty; r < 32; r += 8) {
        float v = t[tx][r];
        __nv_bfloat16 h = __float2bfloat16(v);
        size_t o = (size_t)(n0 + r) * K + k0 + tx;
        dh[o] = h;
        dl[o] = __float2bfloat16(v - __bfloat162float(h));
    }
}

// ---------------------------------------------------------------------------
// 3xBF16 GEMM with PRE-SPLIT operands. NOW 3-STAGE cp.async pipeline
// (mechanical extension of the R7-measured 2-stage version: buf = t%3,
//  wait_group keeps up to 2 tiles in flight; end-of-body barrier preserves
//  the WAR distance to buffer reuse at tile t+3).
// ---------------------------------------------------------------------------
#define GW   20
#define GBUF (128 * GW)
#define GSTG 3
#define GARR (GSTG * GBUF)
#define GSMEM_BYTES (4 * GARR * 4)      // 122880 B

__global__ __launch_bounds__(256) void gemm_bf16p(
    const __nv_bfloat16* __restrict__ Ah, const __nv_bfloat16* __restrict__ Al,
    const __nv_bfloat16* __restrict__ Bh, const __nv_bfloat16* __restrict__ Bl,
    float* __restrict__ C, int M, int N, int K,
    const float* __restrict__ bias)
{
    extern __shared__ uint32_t smp[];
    const uint32_t sbase = (uint32_t)__cvta_generic_to_shared(smp);
    const uint32_t bAh = 0, bAl = GARR, bBh = 2 * GARR, bBl = 3 * GARR;

    const int bm = blockIdx.y * 128;
    const int bn = blockIdx.x * 128;
    const int tid = threadIdx.x;
    const int wid = tid >> 5, lane = tid & 31;
    const int wm = (wid & 1) * 64;
    const int wn = (wid >> 1) * 32;
    const int gq = lane >> 2, tg = lane & 3;

    const int arow = (lane & 7) | (lane & 8);
    const int awrd = (lane & 16) ? 4 : 0;
    const int brow = (lane & 7) | ((lane & 16) >> 1);
    const int bwrd = (lane & 8) ? 4 : 0;

    const int srow = tid >> 1, shalf = tid & 1;
    const __nv_bfloat16* gah = Ah + (size_t)(bm + srow) * K + shalf * 16;
    const __nv_bfloat16* gal = Al + (size_t)(bm + srow) * K + shalf * 16;
    const __nv_bfloat16* gbh = Bh + (size_t)(bn + srow) * K + shalf * 16;
    const __nv_bfloat16* gbl = Bl + (size_t)(bn + srow) * K + shalf * 16;
    const uint32_t swoff = (srow * GW + shalf * 8) * 4;

    float acc[4][4][4] = {};

    auto issue_tile = [&](int t, int b) {
        const int koff = t * 32;
        const uint32_t bb = b * GBUF * 4;
        cpasync16(sbase + bAh * 4 + bb + swoff,      gah + koff);
        cpasync16(sbase + bAh * 4 + bb + swoff + 16, gah + koff + 8);
        cpasync16(sbase + bAl * 4 + bb + swoff,      gal + koff);
        cpasync16(sbase + bAl * 4 + bb + swoff + 16, gal + koff + 8);
        cpasync16(sbase + bBh * 4 + bb + swoff,      gbh + koff);
        cpasync16(sbase + bBh * 4 + bb + swoff + 16, gbh + koff + 8);
        cpasync16(sbase + bBl * 4 + bb + swoff,      gbl + koff);
        cpasync16(sbase + bBl * 4 + bb + swoff + 16, gbl + koff + 8);
        asm volatile("cp.async.commit_group;" ::: "memory");
    };

    const int NT = K / 32;
    issue_tile(0, 0);
    if (NT > 1) issue_tile(1, 1);

    for (int t = 0; t < NT; t++) {
        if (t + 2 < NT) {
            issue_tile(t + 2, (t + 2) % GSTG);
            asm volatile("cp.async.wait_group 2;" ::: "memory");   // tile t done
        } else if (t + 2 == NT) {
            asm volatile("cp.async.wait_group 1;" ::: "memory");
        } else {
            asm volatile("cp.async.wait_group 0;" ::: "memory");
        }
        __syncthreads();

        const uint32_t bb = (t % GSTG) * GBUF * 4;
        #pragma unroll
        for (int kk = 0; kk < 2; kk++) {
            const int kbw = kk * 8;
            uint32_t ah[4][4], al[4][4];
            #pragma unroll
            for (int ma = 0; ma < 4; ma++) {
                uint32_t ro = ((wm + ma * 16 + arow) * GW + kbw + awrd) * 4;
                ldsm4(ah[ma], sbase + bAh * 4 + bb + ro);
                ldsm4(al[ma], sbase + bAl * 4 + bb + ro);
            }
            uint32_t bh[2][4], bl[2][4];
            #pragma unroll
            for (int np = 0; np < 2; np++) {
                uint32_t ro = ((wn + np * 16 + brow) * GW + kbw + bwrd) * 4;
                ldsm4(bh[np], sbase + bBh * 4 + bb + ro);
                ldsm4(bl[np], sbase + bBl * 4 + bb + ro);
            }
            #pragma unroll
            for (int na = 0; na < 4; na++) {
                uint32_t bh0 = bh[na >> 1][(na & 1) * 2], bh1 = bh[na >> 1][(na & 1) * 2 + 1];
                uint32_t bl0 = bl[na >> 1][(na & 1) * 2], bl1 = bl[na >> 1][(na & 1) * 2 + 1];
                #pragma unroll
                for (int ma = 0; ma < 4; ma++) {
                    mma_bf16(acc[ma][na], ah[ma], bh0, bh1);
                    mma_bf16(acc[ma][na], ah[ma], bl0, bl1);
                    mma_bf16(acc[ma][na], al[ma], bh0, bh1);
                }
            }
        }
        __syncthreads();   // all reads of buffer t done before tile t+3 reuses it
    }

    #pragma unroll
    for (int ma = 0; ma < 4; ma++) {
        int r0 = bm + wm + ma * 16 + gq;
        #pragma unroll
        for (int na = 0; na < 4; na++) {
            int c = bn + wn + na * 8 + 2 * tg;
            float b0 = bias ? bias[c] : 0.f;
            float b1 = bias ? bias[c + 1] : 0.f;
            C[(size_t)r0 * N + c]           = acc[ma][na][0] + b0;
            C[(size_t)r0 * N + c + 1]       = acc[ma][na][1] + b1;
            C[(size_t)(r0 + 8) * N + c]     = acc[ma][na][2] + b0;
            C[(size_t)(r0 + 8) * N + c + 1] = acc[ma][na][3] + b1;
        }
    }
}

// ---------------------------------------------------------------------------
// Rotary + layout transform: (b,n,h*d) -> (b,h,n,d); q scaled by QK_SCALE.
// Writes tf32-ROUNDED values so flash can stage without conversion.
// ---------------------------------------------------------------------------
__global__ __launch_bounds__(256) void rotary_kernel(
    const float* __restrict__ qp, const float* __restrict__ kvp,
    const float* __restrict__ freqs)
{
    int i = blockIdx.x * blockDim.x + threadIdx.x;
    const int total = B_ * NH * SEQ * (HD / 2);
    if (i >= total) return;

    int p = i & (HD / 2 - 1);
    int r = i >> 6;
    int n = r & (SEQ - 1); r >>= 11;
    int h = r & (NH - 1);
    int b = r >> 4;
    int d0 = 2 * p;

    float f0 = freqs[n * HD + d0];
    float f1 = freqs[n * HD + d0 + 1];
    float c0 = cosf(f0), s0 = sinf(f0);
    float c1 = cosf(f1), s1 = sinf(f1);

    size_t qsrc = ((size_t)b * SEQ + n) * INNER + h * HD + d0;
    size_t ksrc = ((size_t)b * SEQ + n) * (2 * INNER) + h * HD + d0;
    size_t dst  = (((size_t)b * NH + h) * SEQ + n) * HD + d0;

    float q0 = qp[qsrc], q1 = qp[qsrc + 1];
    g_q[dst]     = tf32_round((q0 * c0 - q1 * s0) * QK_SCALE);
    g_q[dst + 1] = tf32_round((q1 * c1 + q0 * s1) * QK_SCALE);

    float k0 = kvp[ksrc], k1 = kvp[ksrc + 1];
    g_k[dst]     = tf32_round(k0 * c0 - k1 * s0);
    g_k[dst + 1] = tf32_round(k1 * c1 + k0 * s1);

    g_v[dst]     = tf32_round(kvp[ksrc + INNER]);
    g_v[dst + 1] = tf32_round(kvp[ksrc + INNER + 1]);
}

// ---------------------------------------------------------------------------
// Flash attention v2: tf32 mma, Q fragments in registers, cp.async staggered
// K/V pipeline (V load under QK compute, next-K load under PV compute).
// Math identical to R7 (same tf32 rounding points) -> same rel_err.
// ---------------------------------------------------------------------------
#define KSTR 132
#define VSTR 136
#define PSTR 68

__global__ __launch_bounds__(128, 2) void flash_mma2()
{
    extern __shared__ float smem[];
    float* sK = smem;                     // 64*KSTR
    float* sV = sK + 64 * KSTR;           // 64*VSTR
    float* sP = sV + 64 * VSTR;           // 64*PSTR

    const uint32_t skb = (uint32_t)__cvta_generic_to_shared(sK);
    const uint32_t svb = (uint32_t)__cvta_generic_to_shared(sV);

    const int qt  = blockIdx.x;
    const int bh  = blockIdx.y;
    const int tid = threadIdx.x;
    const int wid = tid >> 5, lane = tid & 31;
    const int gq = lane >> 2, tg = lane & 3;
    const int wrow = wid * 16;

    const float* Q  = g_q + ((size_t)bh * SEQ + (size_t)qt * 64) * HD;
    const float* Kp = g_k + (size_t)bh * SEQ * HD;
    const float* Vp = g_v + (size_t)bh * SEQ * HD;

    // ---- Q fragments direct from gmem into registers (one-time; pre-rounded)
    uint32_t qa[16][4];
    {
        const float* qr0 = Q + (size_t)(wrow + gq) * HD;
        const float* qr1 = Q + (size_t)(wrow + gq + 8) * HD;
        #pragma unroll
        for (int ka = 0; ka < 16; ka++) {
            qa[ka][0] = __float_as_uint(qr0[8 * ka + tg]);
            qa[ka][1] = __float_as_uint(qr1[8 * ka + tg]);
            qa[ka][2] = __float_as_uint(qr0[8 * ka + tg + 4]);
            qa[ka][3] = __float_as_uint(qr1[8 * ka + tg + 4]);
        }
    }

    float oacc[16][4] = {};
    float m0 = -1e30f, m1 = -1e30f, l0 = 0.f, l1 = 0.f;

    // tile loader: 64 rows x 128 floats via 16B cp.async (2048 chunks/128 thr)
    auto load_tile = [&](const float* src, uint32_t sdst, int rstride_bytes) {
        for (int i = tid; i < 2048; i += 128) {
            int r = i >> 5, q = i & 31;
            cpasync16(sdst + r * rstride_bytes + q * 16, src + r * HD + q * 4);
        }
        asm volatile("cp.async.commit_group;" ::: "memory");
    };

    load_tile(Kp, skb, KSTR * 4);         // K(0)

    for (int j = 0; j < SEQ; j += 64) {
        // ---- K(j) ready
        asm volatile("cp.async.wait_group 0;" ::: "memory");
        __syncthreads();

        load_tile(Vp + (size_t)j * HD, svb, VSTR * 4);   // V(j) in flight

        // ---- S = Q K^T
        float sacc[8][4] = {};
        #pragma unroll
        for (int ka = 0; ka < 16; ka++) {
            const int kb = ka * 8;
            #pragma unroll
            for (int na = 0; na < 8; na++) {
                uint32_t b0 = __float_as_uint(sK[(na * 8 + gq) * KSTR + kb + tg    ]);
                uint32_t b1 = __float_as_uint(sK[(na * 8 + gq) * KSTR + kb + tg + 4]);
                mma_tf32(sacc[na], qa[ka], b0, b1);
            }
        }

        // ---- online softmax
        float rmax0 = -1e30f, rmax1 = -1e30f;
        #pragma unroll
        for (int na = 0; na < 8; na++) {
            rmax0 = fmaxf(rmax0, fmaxf(sacc[na][0], sacc[na][1]));
            rmax1 = fmaxf(rmax1, fmaxf(sacc[na][2], sacc[na][3]));
        }
        rmax0 = fmaxf(rmax0, __shfl_xor_sync(0xffffffffu, rmax0, 1));
        rmax0 = fmaxf(rmax0, __shfl_xor_sync(0xffffffffu, rmax0, 2));
        rmax1 = fmaxf(rmax1, __shfl_xor_sync(0xffffffffu, rmax1, 1));
        rmax1 = fmaxf(rmax1, __shfl_xor_sync(0xffffffffu, rmax1, 2));

        float nm0 = fmaxf(m0, rmax0), nm1 = fmaxf(m1, rmax1);
        float al0 = __expf(m0 - nm0), al1 = __expf(m1 - nm1);
        float ls0 = 0.f, ls1 = 0.f;
        #pragma unroll
        for (int na = 0; na < 8; na++) {
            float p0 = __expf(sacc[na][0] - nm0);
            float p1 = __expf(sacc[na][1] - nm0);
            float p2 = __expf(sacc[na][2] - nm1);
            float p3 = __expf(sacc[na][3] - nm1);
            ls0 += p0 + p1; ls1 += p2 + p3;
            int c = na * 8 + 2 * tg;
            sP[(wrow + gq    ) * PSTR + c    ] = tf32_round(p0);
            sP[(wrow + gq    ) * PSTR + c + 1] = tf32_round(p1);
            sP[(wrow + gq + 8) * PSTR + c    ] = tf32_round(p2);
            sP[(wrow + gq + 8) * PSTR + c + 1] = tf32_round(p3);
        }
        ls0 += __shfl_xor_sync(0xffffffffu, ls0, 1);
        ls0 += __shfl_xor_sync(0xffffffffu, ls0, 2);
        ls1 += __shfl_xor_sync(0xffffffffu, ls1, 1);
        ls1 += __shfl_xor_sync(0xffffffffu, ls1, 2);
        l0 = l0 * al0 + ls0;
        l1 = l1 * al1 + ls1;
        m0 = nm0; m1 = nm1;

        #pragma unroll
        for (int na = 0; na < 16; na++) {
            oacc[na][0] *= al0; oacc[na][1] *= al0;
            oacc[na][2] *= al1; oacc[na][3] *= al1;
        }

        // ---- V(j) ready; sync also publishes sP and retires all K reads
        asm volatile("cp.async.wait_group 0;" ::: "memory");
        __syncthreads();

        if (j + 64 < SEQ)
            load_tile(Kp + (size_t)(j + 64) * HD, skb, KSTR * 4);   // K(j+1) in flight

        // ---- O += P @ V
        #pragma unroll
        for (int ka = 0; ka < 8; ka++) {
            const int kb = ka * 8;
            uint32_t a[4];
            a[0] = __float_as_uint(sP[(wrow + gq    ) * PSTR + kb + tg    ]);
            a[1] = __float_as_uint(sP[(wrow + gq + 8) * PSTR + kb + tg    ]);
            a[2] = __float_as_uint(sP[(wrow + gq    ) * PSTR + kb + tg + 4]);
            a[3] = __float_as_uint(sP[(wrow + gq + 8) * PSTR + kb + tg + 4]);
            #pragma unroll
            for (int na = 0; na < 16; na++) {
                uint32_t b0 = __float_as_uint(sV[(kb + tg    ) * VSTR + na * 8 + gq]);
                uint32_t b1 = __float_as_uint(sV[(kb + tg + 4) * VSTR + na * 8 + gq]);
                mma_tf32(oacc[na], a, b0, b1);
            }
        }
        // next iteration's top sync retires V reads before V(j+1) overwrite
    }

    // ---- epilogue: normalize, write bf16 hi/lo to (b,n,h*d)
    const int b = bh >> 4, h = bh & 15;
    const float inv0 = 1.f / l0, inv1 = 1.f / l1;
    const int r0 = qt * 64 + wrow + gq;
    #pragma unroll
    for (int na = 0; na < 16; na++) {
        int c = h * HD + na * 8 + 2 * tg;
        size_t base0 = ((size_t)b * SEQ + r0) * INNER + c;
        size_t base1 = ((size_t)b * SEQ + r0 + 8) * INNER + c;
        float v00 = oacc[na][0] * inv0, v01 = oacc[na][1] * inv0;
        float v10 = oacc[na][2] * inv1, v11 = oacc[na][3] * inv1;
        __nv_bfloat16 hh;
        hh = __float2bfloat16(v00); g_aoh[base0]     = hh; g_aol[base0]     = __float2bfloat16(v00 - __bfloat162float(hh));
        hh = __float2bfloat16(v01); g_aoh[base0 + 1] = hh; g_aol[base0 + 1] = __float2bfloat16(v01 - __bfloat162float(hh));
        hh = __float2bfloat16(v10); g_aoh[base1]     = hh; g_aol[base1]     = __float2bfloat16(v10 - __bfloat162float(hh));
        hh = __float2bfloat16(v11); g_aoh[base1 + 1] = hh; g_aol[base1 + 1] = __float2bfloat16(v11 - __bfloat162float(hh));
    }
}

// ---------------------------------------------------------------------------
extern "C" void kernel_launch(void* const* d_in, const int* in_sizes, int n_in,
                              void* d_out, int out_size)
{
    const float* x   = (const float*)d_in[0];
    const float* rot = (const float*)d_in[1];
    const float* Wq  = (const float*)d_in[2];
    const float* Wkv = (const float*)d_in[3];
    const float* Wo  = (const float*)d_in[4];
    const float* bo  = (const float*)d_in[5];
    float* out = (float*)d_out;

    float *qproj, *kv;
    cudaGetSymbolAddress((void**)&qproj, g_qproj);
    cudaGetSymbolAddress((void**)&kv,   g_kv);
    __nv_bfloat16 *xh, *xl, *wqh, *wql, *wkvh, *wkvl, *woh, *wol, *aoh, *aol;
    cudaGetSymbolAddress((void**)&xh,  g_xh);   cudaGetSymbolAddress((void**)&xl,  g_xl);
    cudaGetSymbolAddress((void**)&wqh, g_wqh);  cudaGetSymbolAddress((void**)&wql, g_wql);
    cudaGetSymbolAddress((void**)&wkvh, g_wkvh); cudaGetSymbolAddress((void**)&wkvl, g_wkvl);
    cudaGetSymbolAddress((void**)&woh, g_woh);  cudaGetSymbolAddress((void**)&wol, g_wol);
    cudaGetSymbolAddress((void**)&aoh, g_aoh);  cudaGetSymbolAddress((void**)&aol, g_aol);

    const int M = B_ * SEQ;   // 4096

    // 0) pre-split operands
    {
        int n4 = M * DIM / 4;
        splitHL<<<(n4 + 255) / 256, 256>>>((const float4*)x, xh, xl, n4);
        convT<<<dim3(INNER / 32,     DIM / 32), 256>>>(Wq,  wqh,  wql,  DIM,   INNER);
        convT<<<dim3(2 * INNER / 32, DIM / 32), 256>>>(Wkv, wkvh, wkvl, DIM,   2 * INNER);
        convT<<<dim3(DIM / 32,     INNER / 32), 256>>>(Wo,  woh,  wol,  INNER, DIM);
    }

    cudaFuncSetAttribute(gemm_bf16p, cudaFuncAttributeMaxDynamicSharedMemorySize, GSMEM_BYTES);

    // 1) Q = x @ Wq
    gemm_bf16p<<<dim3(INNER / 128, M / 128), 256, GSMEM_BYTES>>>(
        xh, xl, wqh, wql, qproj, M, INNER, DIM, nullptr);
    // 2) KV = x @ Wkv
    gemm_bf16p<<<dim3(2 * INNER / 128, M / 128), 256, GSMEM_BYTES>>>(
        xh, xl, wkvh, wkvl, kv, M, 2 * INNER, DIM, nullptr);
    // 3) rotary + layout (writes tf32-rounded q/k/v)
    {
        int total = B_ * NH * SEQ * (HD / 2);
        rotary_kernel<<<total / 256, 256>>>(qproj, kv, rot);
    }
    // 4) flash attention v2 -> writes aoh/aol
    {
        size_t smemb = (size_t)(64 * KSTR + 64 * VSTR + 64 * PSTR) * sizeof(float);
        cudaFuncSetAttribute(flash_mma2, cudaFuncAttributeMaxDynamicSharedMemorySize, (int)smemb);
        flash_mma2<<<dim3(SEQ / 64, B_ * NH), 128, smemb>>>();
    }
    // 5) out = ao @ Wo + bo
    gemm_bf16p<<<dim3(DIM / 128, M / 128), 256, GSMEM_BYTES>>>(
        aoh, aol, woh, wol, out, M, DIM, INNER, bo);
}